// round 1
// baseline (speedup 1.0000x reference)
#include <cuda_runtime.h>

typedef unsigned long long u64;

#define BATCH  4096
#define DIN    512
#define NTREES 64
#define NINT   63
#define NCOLS  4032          // NINT * NTREES
#define KLT    4096          // NLEAF * NTREES
#define LDIM   128
#define SPLITK 4

// ---- scratch (static device globals: allocation-free kernel_launch) ----
__device__ float g_buf[(size_t)BATCH * NCOLS];        // sigmoid gate values  [b][n*64+t]
__device__ float p_buf[(size_t)BATCH * KLT];          // leaf probabilities   [b][l*64+t]
__device__ float w2_buf[(size_t)KLT * LDIM];          // leaf_weight*softmax  [l*64+t][d]
__device__ float part_buf[SPLITK * (size_t)BATCH * LDIM];  // split-K partials

// ---- packed fp32x2 helpers (Blackwell FFMA2 path) ----
__device__ __forceinline__ void fma2(u64 &d, u64 a, u64 b) {
    asm("fma.rn.f32x2 %0, %1, %2, %0;" : "+l"(d) : "l"(a), "l"(b));
}
__device__ __forceinline__ u64 dup2(float x) {
    u64 r;
    unsigned int xi = __float_as_uint(x);
    asm("mov.b64 %0, {%1, %1};" : "=l"(r) : "r"(xi));
    return r;
}
__device__ __forceinline__ float sigf(float z) {
    return 1.0f / (1.0f + expf(-z));
}

// ============================================================================
// Kernel 1: g = sigmoid(x @ Wmat + bias)
//   A = x [4096,512] row-major, B[k][col] = W[col/64][k][col%64], C = g_buf
//   Tiles: BM=128, BN=128, BK=16, 256 threads, 8x8 per thread via f32x2 pairs.
// ============================================================================
__global__ __launch_bounds__(256, 2)
void gemm1_kernel(const float* __restrict__ x, const float* __restrict__ W,
                  const float* __restrict__ bias) {
    __shared__ float As[16][128];   // transposed: As[k][m]
    __shared__ float Bs[16][128];

    const int tid = threadIdx.x;
    const int tx = tid & 15;        // 16 col-groups of 8
    const int ty = tid >> 4;        // 16 row-groups of 8
    const int bm = blockIdx.y * 128;
    const int bn = blockIdx.x * 128;

    // global-load mapping
    const int a_row = tid >> 2;          // 0..63 (+64 second item)
    const int a_c4  = (tid & 3) * 4;     // k offset within tile
    const int b_k   = tid >> 5;          // 0..7 (+8 second item)
    const int b_c   = (tid & 31) * 4;    // col offset within tile

    const float* Ap = x + (size_t)(bm + a_row) * DIN + a_c4;
    const int   colg   = bn + b_c;
    const bool  bvalid = (colg < NCOLS);
    const int   n_idx  = colg >> 6;
    const int   t_idx  = colg & 63;
    const float* Bp = W + (size_t)n_idx * (DIN * NTREES) + (size_t)b_k * NTREES + t_idx;

    u64 acc[4][8];
    #pragma unroll
    for (int i = 0; i < 4; i++)
        #pragma unroll
        for (int j = 0; j < 8; j++) acc[i][j] = 0ull;

    float4 ra0, ra1, rb0, rb1;
    ra0 = *(const float4*)(Ap);
    ra1 = *(const float4*)(Ap + 64 * DIN);
    rb0 = make_float4(0.f, 0.f, 0.f, 0.f);
    rb1 = rb0;
    if (bvalid) {
        rb0 = *(const float4*)(Bp);
        rb1 = *(const float4*)(Bp + 8 * NTREES);
    }

    const int NKT = DIN / 16;  // 32
    for (int kt = 0; kt < NKT; kt++) {
        // stage registers -> smem
        As[a_c4 + 0][a_row] = ra0.x;
        As[a_c4 + 1][a_row] = ra0.y;
        As[a_c4 + 2][a_row] = ra0.z;
        As[a_c4 + 3][a_row] = ra0.w;
        As[a_c4 + 0][a_row + 64] = ra1.x;
        As[a_c4 + 1][a_row + 64] = ra1.y;
        As[a_c4 + 2][a_row + 64] = ra1.z;
        As[a_c4 + 3][a_row + 64] = ra1.w;
        *(float4*)&Bs[b_k][b_c]     = rb0;
        *(float4*)&Bs[b_k + 8][b_c] = rb1;
        __syncthreads();

        // prefetch next tile while computing
        if (kt + 1 < NKT) {
            const float* Ap2 = Ap + (kt + 1) * 16;
            ra0 = *(const float4*)(Ap2);
            ra1 = *(const float4*)(Ap2 + 64 * DIN);
            if (bvalid) {
                const float* Bp2 = Bp + (size_t)(kt + 1) * 16 * NTREES;
                rb0 = *(const float4*)(Bp2);
                rb1 = *(const float4*)(Bp2 + 8 * NTREES);
            }
        }

        #pragma unroll
        for (int k = 0; k < 16; k++) {
            ulonglong2 a01 = *(const ulonglong2*)&As[k][ty * 8];
            ulonglong2 a23 = *(const ulonglong2*)&As[k][ty * 8 + 4];
            u64 ap[4] = { a01.x, a01.y, a23.x, a23.y };
            float4 bv0 = *(const float4*)&Bs[k][tx * 8];
            float4 bv1 = *(const float4*)&Bs[k][tx * 8 + 4];
            u64 bd[8] = { dup2(bv0.x), dup2(bv0.y), dup2(bv0.z), dup2(bv0.w),
                          dup2(bv1.x), dup2(bv1.y), dup2(bv1.z), dup2(bv1.w) };
            #pragma unroll
            for (int rp = 0; rp < 4; rp++)
                #pragma unroll
                for (int c = 0; c < 8; c++)
                    fma2(acc[rp][c], ap[rp], bd[c]);
        }
        __syncthreads();
    }

    // epilogue: + bias, sigmoid, store
    const int colb = bn + tx * 8;
    if (colb < NCOLS) {
        float bb[8];
        #pragma unroll
        for (int c = 0; c < 8; c++) bb[c] = bias[colb + c];

        #pragma unroll
        for (int rp = 0; rp < 4; rp++) {
            const int row = bm + ty * 8 + rp * 2;
            float2 v[8];
            #pragma unroll
            for (int c = 0; c < 8; c++) v[c] = *(float2*)&acc[rp][c];

            float* gr0 = g_buf + (size_t)row * NCOLS + colb;
            float* gr1 = gr0 + NCOLS;
            float4 o;
            o = make_float4(sigf(v[0].x + bb[0]), sigf(v[1].x + bb[1]),
                            sigf(v[2].x + bb[2]), sigf(v[3].x + bb[3]));
            *(float4*)gr0 = o;
            o = make_float4(sigf(v[4].x + bb[4]), sigf(v[5].x + bb[5]),
                            sigf(v[6].x + bb[6]), sigf(v[7].x + bb[7]));
            *(float4*)(gr0 + 4) = o;
            o = make_float4(sigf(v[0].y + bb[0]), sigf(v[1].y + bb[1]),
                            sigf(v[2].y + bb[2]), sigf(v[3].y + bb[3]));
            *(float4*)gr1 = o;
            o = make_float4(sigf(v[4].y + bb[4]), sigf(v[5].y + bb[5]),
                            sigf(v[6].y + bb[6]), sigf(v[7].y + bb[7]));
            *(float4*)(gr1 + 4) = o;
        }
    }
}

// ============================================================================
// Kernel 2: tree propagation.  One thread per (b, t).
//   p[2i]   = p[i] * g[node]
//   p[2i+1] = p[i] * (1 - g[node]),  node = (2^L - 1) + i, i descending.
// ============================================================================
__global__ __launch_bounds__(256)
void prop_kernel() {
    const int id = blockIdx.x * blockDim.x + threadIdx.x;   // 0 .. 262143
    const int t = id & 63;
    const int b = id >> 6;

    const float* g = g_buf + (size_t)b * NCOLS + t;
    float p[64];
    p[0] = 1.0f;

    #pragma unroll
    for (int level = 0; level < 6; level++) {
        const int nl = 1 << level;
        const int st = nl - 1;
        #pragma unroll
        for (int i = nl - 1; i >= 0; i--) {
            const float gg = g[(size_t)(st + i) * 64];
            const float pi = p[i];
            p[2 * i + 1] = pi * (1.0f - gg);
            p[2 * i]     = pi * gg;
        }
    }

    float* outp = p_buf + (size_t)b * KLT + t;
    #pragma unroll
    for (int l = 0; l < 64; l++) outp[(size_t)l * 64] = p[l];
}

// ============================================================================
// Kernel 3: w2[(l*64+t)][d] = leaf_weight[l][d][t] * softmax_t(gates[l][d][:])
//   One 64-thread block per (l, d).
// ============================================================================
__global__ __launch_bounds__(64)
void w2_kernel(const float* __restrict__ leaf_weight, const float* __restrict__ gates) {
    const int l = blockIdx.x / LDIM;
    const int d = blockIdx.x % LDIM;
    const int t = threadIdx.x;

    const size_t base = ((size_t)l * LDIM + d) * NTREES + t;
    const float gv = gates[base];

    __shared__ float red[64];
    red[t] = gv;
    __syncthreads();
    #pragma unroll
    for (int s = 32; s > 0; s >>= 1) {
        if (t < s) red[t] = fmaxf(red[t], red[t + s]);
        __syncthreads();
    }
    const float mx = red[0];
    __syncthreads();

    const float e = expf(gv - mx);
    red[t] = e;
    __syncthreads();
    #pragma unroll
    for (int s = 32; s > 0; s >>= 1) {
        if (t < s) red[t] += red[t + s];
        __syncthreads();
    }
    const float inv = 1.0f / red[0];

    w2_buf[((size_t)l * 64 + t) * LDIM + d] = leaf_weight[base] * e * inv;
}

// ============================================================================
// Kernel 4: split-K GEMM2 partials.
//   part[z][b][d] = sum_{k in chunk z} p_buf[b][k] * w2_buf[k][d]
//   Tiles: BM=64, BN=128(full), BK=16, split-K=4, 256 threads, 8x4 per thread.
// ============================================================================
__global__ __launch_bounds__(256, 2)
void gemm2_kernel() {
    __shared__ float As[16][64];    // transposed
    __shared__ float Bs[16][128];

    const int tid = threadIdx.x;
    const int tx = tid & 31;        // 32 col-groups of 4
    const int ty = tid >> 5;        // 8 row-groups of 8
    const int bm = blockIdx.x * 64;
    const int kz = blockIdx.y;                  // 0..3
    const int k0base = kz * (KLT / SPLITK);     // 1024 per chunk

    const int a_row = tid >> 2;          // 0..63
    const int a_c4  = (tid & 3) * 4;
    const int b_k   = tid >> 5;          // 0..7 (+8)
    const int b_c   = (tid & 31) * 4;

    const float* Ap = p_buf + (size_t)(bm + a_row) * KLT + k0base + a_c4;
    const float* Bp = w2_buf + (size_t)(k0base + b_k) * LDIM + b_c;

    u64 acc[4][4];
    #pragma unroll
    for (int i = 0; i < 4; i++)
        #pragma unroll
        for (int j = 0; j < 4; j++) acc[i][j] = 0ull;

    float4 ra  = *(const float4*)Ap;
    float4 rb0 = *(const float4*)Bp;
    float4 rb1 = *(const float4*)(Bp + 8 * LDIM);

    const int NKT = (KLT / SPLITK) / 16;  // 64
    for (int kt = 0; kt < NKT; kt++) {
        As[a_c4 + 0][a_row] = ra.x;
        As[a_c4 + 1][a_row] = ra.y;
        As[a_c4 + 2][a_row] = ra.z;
        As[a_c4 + 3][a_row] = ra.w;
        *(float4*)&Bs[b_k][b_c]     = rb0;
        *(float4*)&Bs[b_k + 8][b_c] = rb1;
        __syncthreads();

        if (kt + 1 < NKT) {
            ra  = *(const float4*)(Ap + (kt + 1) * 16);
            const float* Bp2 = Bp + (size_t)(kt + 1) * 16 * LDIM;
            rb0 = *(const float4*)(Bp2);
            rb1 = *(const float4*)(Bp2 + 8 * LDIM);
        }

        #pragma unroll
        for (int k = 0; k < 16; k++) {
            ulonglong2 a01 = *(const ulonglong2*)&As[k][ty * 8];
            ulonglong2 a23 = *(const ulonglong2*)&As[k][ty * 8 + 4];
            u64 ap[4] = { a01.x, a01.y, a23.x, a23.y };
            float4 bv = *(const float4*)&Bs[k][tx * 4];
            u64 bd[4] = { dup2(bv.x), dup2(bv.y), dup2(bv.z), dup2(bv.w) };
            #pragma unroll
            for (int rp = 0; rp < 4; rp++)
                #pragma unroll
                for (int c = 0; c < 4; c++)
                    fma2(acc[rp][c], ap[rp], bd[c]);
        }
        __syncthreads();
    }

    float* outp = part_buf + (size_t)kz * (BATCH * LDIM);
    #pragma unroll
    for (int rp = 0; rp < 4; rp++) {
        const int row = bm + ty * 8 + rp * 2;
        float2 v[4];
        #pragma unroll
        for (int c = 0; c < 4; c++) v[c] = *(float2*)&acc[rp][c];
        float* o0 = outp + (size_t)row * LDIM + tx * 4;
        *(float4*)o0          = make_float4(v[0].x, v[1].x, v[2].x, v[3].x);
        *(float4*)(o0 + LDIM) = make_float4(v[0].y, v[1].y, v[2].y, v[3].y);
    }
}

// ============================================================================
// Kernel 5: deterministic split-K reduce into d_out.
// ============================================================================
__global__ __launch_bounds__(256)
void reduce_kernel(float* __restrict__ out) {
    const int i = blockIdx.x * blockDim.x + threadIdx.x;
    const size_t S = (size_t)BATCH * LDIM;
    out[i] = part_buf[i] + part_buf[i + S] + part_buf[i + 2 * S] + part_buf[i + 3 * S];
}

// ============================================================================
extern "C" void kernel_launch(void* const* d_in, const int* in_sizes, int n_in,
                              void* d_out, int out_size) {
    (void)in_sizes; (void)n_in; (void)out_size;
    const float* x     = (const float*)d_in[0];
    const float* W     = (const float*)d_in[1];
    const float* bias  = (const float*)d_in[2];
    const float* lw    = (const float*)d_in[3];
    const float* gates = (const float*)d_in[4];
    float* out = (float*)d_out;

    dim3 g1((NCOLS + 127) / 128, BATCH / 128);   // 32 x 32
    gemm1_kernel<<<g1, 256>>>(x, W, bias);

    prop_kernel<<<(BATCH * NTREES) / 256, 256>>>();

    w2_kernel<<<64 * LDIM, 64>>>(lw, gates);

    dim3 g2(BATCH / 64, SPLITK);                 // 64 x 4
    gemm2_kernel<<<g2, 256>>>();

    reduce_kernel<<<(BATCH * LDIM) / 256, 256>>>(out);
}

// round 3
// speedup vs baseline: 1.7268x; 1.7268x over previous
#include <cuda_runtime.h>
#include <cuda_bf16.h>
#include <cstdint>

typedef unsigned long long u64;
typedef unsigned int u32;

#define BATCH   4096
#define DIN     512
#define NTREES  64
#define NCOLSV  4032        // valid gate columns
#define GCOLS   4096        // padded gate columns
#define KLT     4096
#define LDIM    128
#define SPLITK2 8

// ---------------- scratch (device globals: allocation-free) ----------------
__device__ float g_buf[(size_t)BATCH * GCOLS];     // sigmoid gates [b][col], padded
__device__ float p_buf[(size_t)BATCH * KLT];       // leaf probs    [b][l*64+t]
__device__ float wt_buf[(size_t)GCOLS * DIN];      // W transposed  [col][k], padded cols zero
__device__ float w2t_buf[(size_t)LDIM * KLT];      // leaf_w*softmax transposed [d][k]
__device__ float part_buf[SPLITK2 * (size_t)BATCH * LDIM];

// ---------------- helpers ----------------
__device__ __forceinline__ u32 smem_u32(const void* p) {
    u32 a;
    asm("{ .reg .u64 t; cvta.to.shared.u64 t, %1; cvt.u32.u64 %0, t; }" : "=r"(a) : "l"(p));
    return a;
}
__device__ __forceinline__ float sigf(float z) { return 1.0f / (1.0f + expf(-z)); }

// pack two floats' bf16-hi parts and bf16-lo residuals into u32s
__device__ __forceinline__ void split2(float a, float b, u32 &hi, u32 &lo) {
    __nv_bfloat16 ha = __float2bfloat16(a);
    __nv_bfloat16 hb = __float2bfloat16(b);
    float ra = a - __bfloat162float(ha);
    float rb = b - __bfloat162float(hb);
    __nv_bfloat16 la = __float2bfloat16(ra);
    __nv_bfloat16 lb = __float2bfloat16(rb);
    hi = (u32)__bfloat16_as_ushort(ha) | ((u32)__bfloat16_as_ushort(hb) << 16);
    lo = (u32)__bfloat16_as_ushort(la) | ((u32)__bfloat16_as_ushort(lb) << 16);
}

#define LDSM_X4(r0, r1, r2, r3, addr) \
    asm volatile("ldmatrix.sync.aligned.m8n8.x4.shared.b16 {%0,%1,%2,%3}, [%4];" \
                 : "=r"(r0), "=r"(r1), "=r"(r2), "=r"(r3) : "r"(addr))

#define MMA16816(d, a, b0, b1) \
    asm volatile("mma.sync.aligned.m16n8k16.row.col.f32.bf16.bf16.f32 " \
                 "{%0,%1,%2,%3}, {%4,%5,%6,%7}, {%8,%9}, {%0,%1,%2,%3};" \
                 : "+f"((d)[0]), "+f"((d)[1]), "+f"((d)[2]), "+f"((d)[3]) \
                 : "r"((a)[0]), "r"((a)[1]), "r"((a)[2]), "r"((a)[3]), \
                   "r"(b0), "r"(b1))

// ---------------- bf16x3 tensor-core GEMM ----------------
// C[128,128] CTA tile, 8 warps of 64x32, K-chunks of 32.
// SMEM tiles: [128 rows][32 k] bf16 = 8KB each (AH, AL, BH, BL).
// Swizzle: 16B chunk c' = c ^ ((row>>1)&3); row stride 64B.
#define BM 128
#define BN 128
#define KC 32
#define TILE_B 8192
#define OFF_AH 0
#define OFF_AL 8192
#define OFF_BH 16384
#define OFF_BL 24576
#define OFF_BIAS 32768

// MODE 1: g = sigmoid(x @ wt^T + bias)      grid (32, 32, 1)
// MODE 2: part[z] = p_buf @ w2t^T (split-K) grid (1, 32, 8)
template <int MODE>
__global__ __launch_bounds__(256)
void hmma_kernel(const float* __restrict__ Aext, const float* __restrict__ bias) {
    __shared__ __align__(128) char smem[OFF_BIAS + 512];
    const u32 sb = smem_u32(smem);
    const int tid  = threadIdx.x;
    const int wid  = tid >> 5;
    const int lane = tid & 31;

    const int bn = blockIdx.x * BN;
    const int bm = blockIdx.y * BM;
    const long kbase = (long)blockIdx.z * 512;

    const float* A   = (MODE == 1) ? Aext   : p_buf;
    const float* B   = (MODE == 1) ? wt_buf : w2t_buf;
    const long lda = (MODE == 1) ? (long)DIN : (long)KLT;
    const long ldb = (MODE == 1) ? (long)DIN : (long)KLT;

    if (MODE == 1 && tid < 128) {
        int col = bn + tid;
        ((float*)(smem + OFF_BIAS))[tid] = (col < NCOLSV) ? bias[col] : 0.0f;
    }

    // ---- global load / convert-store mapping (per thread: 2 rows x 8 elems per operand)
    const int r0 = tid >> 2;           // 0..63
    const int cc = tid & 3;            // 16B chunk within 64B row
    const u32 soff0 = (u32)(r0 * 64 + ((cc ^ ((r0 >> 1) & 3)) << 4));
    const u32 soff1 = soff0 + 4096;    // row + 64 (same swizzle bits)

    const float* Abase = A + (size_t)bm * lda + kbase;
    const float* Bbase = B + (size_t)bn * ldb + kbase;
    const float* ga0 = Abase + (size_t)r0 * lda + cc * 8;
    const float* ga1 = ga0 + 64 * lda;
    const float* gb0 = Bbase + (size_t)r0 * ldb + cc * 8;
    const float* gb1 = gb0 + 64 * ldb;

    // ---- ldmatrix addressing (per warp)
    const int mw = (wid & 1) * 64;
    const int nw = (wid >> 1) * 32;
    const int rowA_l = mw + (lane & 15);
    const int rowB_l = (lane & 7) | ((lane >> 1) & 8);
    u32 aoff[2], boff[2];
    #pragma unroll
    for (int kk = 0; kk < 2; kk++) {
        int chA = kk * 2 + (lane >> 4);
        int chB = kk * 2 + ((lane >> 3) & 1);
        aoff[kk] = sb + (u32)(rowA_l * 64 + ((chA ^ ((rowA_l >> 1) & 3)) << 4));
        boff[kk] = sb + (u32)(rowB_l * 64 + ((chB ^ ((rowB_l >> 1) & 3)) << 4)) + (u32)(nw * 64);
    }

    float acc[4][4][4];
    #pragma unroll
    for (int i = 0; i < 4; i++)
        #pragma unroll
        for (int j = 0; j < 4; j++)
            #pragma unroll
            for (int e = 0; e < 4; e++) acc[i][j][e] = 0.0f;

    const int NCH = 16;  // K = 512 per CTA in both modes
    float4 pa0, pa1, pa2, pa3, pb0, pb1, pb2, pb3;

    // preload chunk 0
    pa0 = *(const float4*)(ga0);     pa1 = *(const float4*)(ga0 + 4);
    pa2 = *(const float4*)(ga1);     pa3 = *(const float4*)(ga1 + 4);
    pb0 = *(const float4*)(gb0);     pb1 = *(const float4*)(gb0 + 4);
    pb2 = *(const float4*)(gb1);     pb3 = *(const float4*)(gb1 + 4);

    for (int c = 0; c < NCH; c++) {
        // ---- convert + store to SMEM
        uint4 h, l;
        split2(pa0.x, pa0.y, h.x, l.x); split2(pa0.z, pa0.w, h.y, l.y);
        split2(pa1.x, pa1.y, h.z, l.z); split2(pa1.z, pa1.w, h.w, l.w);
        *(uint4*)(smem + OFF_AH + soff0) = h; *(uint4*)(smem + OFF_AL + soff0) = l;
        split2(pa2.x, pa2.y, h.x, l.x); split2(pa2.z, pa2.w, h.y, l.y);
        split2(pa3.x, pa3.y, h.z, l.z); split2(pa3.z, pa3.w, h.w, l.w);
        *(uint4*)(smem + OFF_AH + soff1) = h; *(uint4*)(smem + OFF_AL + soff1) = l;
        split2(pb0.x, pb0.y, h.x, l.x); split2(pb0.z, pb0.w, h.y, l.y);
        split2(pb1.x, pb1.y, h.z, l.z); split2(pb1.z, pb1.w, h.w, l.w);
        *(uint4*)(smem + OFF_BH + soff0) = h; *(uint4*)(smem + OFF_BL + soff0) = l;
        split2(pb2.x, pb2.y, h.x, l.x); split2(pb2.z, pb2.w, h.y, l.y);
        split2(pb3.x, pb3.y, h.z, l.z); split2(pb3.z, pb3.w, h.w, l.w);
        *(uint4*)(smem + OFF_BH + soff1) = h; *(uint4*)(smem + OFF_BL + soff1) = l;
        __syncthreads();

        // ---- prefetch next chunk (latency hidden under MMA)
        if (c + 1 < NCH) {
            const int o = (c + 1) * KC;
            pa0 = *(const float4*)(ga0 + o);     pa1 = *(const float4*)(ga0 + o + 4);
            pa2 = *(const float4*)(ga1 + o);     pa3 = *(const float4*)(ga1 + o + 4);
            pb0 = *(const float4*)(gb0 + o);     pb1 = *(const float4*)(gb0 + o + 4);
            pb2 = *(const float4*)(gb1 + o);     pb3 = *(const float4*)(gb1 + o + 4);
        }

        // ---- MMA over this chunk: terms AhBh + AlBh + AhBl
        #pragma unroll
        for (int kk = 0; kk < 2; kk++) {
            u32 Ah[4][4], Al[4][4], Bv[8];
            #pragma unroll
            for (int f = 0; f < 4; f++)
                LDSM_X4(Ah[f][0], Ah[f][1], Ah[f][2], Ah[f][3],
                        aoff[kk] + OFF_AH + (u32)(f * 1024));
            #pragma unroll
            for (int g = 0; g < 2; g++)
                LDSM_X4(Bv[4 * g], Bv[4 * g + 1], Bv[4 * g + 2], Bv[4 * g + 3],
                        boff[kk] + OFF_BH + (u32)(g * 1024));
            #pragma unroll
            for (int f = 0; f < 4; f++)
                #pragma unroll
                for (int n = 0; n < 4; n++)
                    MMA16816(acc[f][n], Ah[f], Bv[2 * n], Bv[2 * n + 1]);

            #pragma unroll
            for (int f = 0; f < 4; f++)
                LDSM_X4(Al[f][0], Al[f][1], Al[f][2], Al[f][3],
                        aoff[kk] + OFF_AL + (u32)(f * 1024));
            #pragma unroll
            for (int f = 0; f < 4; f++)
                #pragma unroll
                for (int n = 0; n < 4; n++)
                    MMA16816(acc[f][n], Al[f], Bv[2 * n], Bv[2 * n + 1]);

            #pragma unroll
            for (int g = 0; g < 2; g++)
                LDSM_X4(Bv[4 * g], Bv[4 * g + 1], Bv[4 * g + 2], Bv[4 * g + 3],
                        boff[kk] + OFF_BL + (u32)(g * 1024));
            #pragma unroll
            for (int f = 0; f < 4; f++)
                #pragma unroll
                for (int n = 0; n < 4; n++)
                    MMA16816(acc[f][n], Ah[f], Bv[2 * n], Bv[2 * n + 1]);
        }
        __syncthreads();
    }

    // ---- epilogue
    const float* bias_s = (const float*)(smem + OFF_BIAS);
    #pragma unroll
    for (int f = 0; f < 4; f++) {
        #pragma unroll
        for (int half = 0; half < 2; half++) {
            const int row_l = mw + f * 16 + (lane >> 2) + half * 8;
            #pragma unroll
            for (int n = 0; n < 4; n++) {
                const int col_l = nw + n * 8 + 2 * (lane & 3);
                float v0 = acc[f][n][2 * half + 0];
                float v1 = acc[f][n][2 * half + 1];
                if (MODE == 1) {
                    v0 = sigf(v0 + bias_s[col_l]);
                    v1 = sigf(v1 + bias_s[col_l + 1]);
                    float* o = g_buf + (size_t)(bm + row_l) * GCOLS + bn + col_l;
                    *(float2*)o = make_float2(v0, v1);
                } else {
                    float* o = part_buf + (size_t)blockIdx.z * (BATCH * LDIM)
                             + (size_t)(bm + row_l) * LDIM + bn + col_l;
                    *(float2*)o = make_float2(v0, v1);
                }
            }
        }
    }
}

// ---------------- W transpose: wt_buf[col][k] = W[n][k][t], pad cols>=4032 ----------------
__global__ __launch_bounds__(256)
void transw_kernel(const float* __restrict__ W) {
    const int tid = threadIdx.x;
    const int n = blockIdx.x;      // 0..63 (63 = zero-fill)
    const int kb = blockIdx.y;     // 0..15 (32 k each)
    if (n == 63) {
        #pragma unroll
        for (int i = 0; i < 8; i++) {
            int idx = i * 256 + tid;
            int r = idx >> 5, kk = idx & 31;
            wt_buf[(size_t)(4032 + r) * DIN + kb * 32 + kk] = 0.0f;
        }
        return;
    }
    __shared__ float ts[32][65];
    const int t = tid & 63;
    const int kk0 = tid >> 6;
    #pragma unroll
    for (int i = 0; i < 8; i++) {
        int kk = kk0 + 4 * i;
        ts[kk][t] = W[(size_t)n * (DIN * NTREES) + (size_t)(kb * 32 + kk) * NTREES + t];
    }
    __syncthreads();
    const int kk = tid & 31;
    const int t0 = tid >> 5;
    #pragma unroll
    for (int i = 0; i < 8; i++) {
        int tt = t0 + 8 * i;
        wt_buf[(size_t)(n * 64 + tt) * DIN + kb * 32 + kk] = ts[kk][tt];
    }
}

// ---------------- tree propagation ----------------
__global__ __launch_bounds__(256)
void prop_kernel() {
    const int id = blockIdx.x * blockDim.x + threadIdx.x;
    const int t = id & 63;
    const int b = id >> 6;
    const float* g = g_buf + (size_t)b * GCOLS + t;
    float p[64];
    p[0] = 1.0f;
    #pragma unroll
    for (int level = 0; level < 6; level++) {
        const int nl = 1 << level;
        const int st = nl - 1;
        #pragma unroll
        for (int i = nl - 1; i >= 0; i--) {
            const float gg = g[(size_t)(st + i) * 64];
            const float pi = p[i];
            p[2 * i + 1] = pi * (1.0f - gg);
            p[2 * i]     = pi * gg;
        }
    }
    float* outp = p_buf + (size_t)b * KLT + t;
    #pragma unroll
    for (int l = 0; l < 64; l++) outp[(size_t)l * 64] = p[l];
}

// ---------------- softmax * leaf_weight, transposed store ----------------
__global__ __launch_bounds__(64)
void w2_kernel(const float* __restrict__ leaf_weight, const float* __restrict__ gates) {
    const int l = blockIdx.x / LDIM;
    const int d = blockIdx.x % LDIM;
    const int t = threadIdx.x;
    const size_t base = ((size_t)l * LDIM + d) * NTREES + t;
    const float gv = gates[base];
    __shared__ float red[64];
    red[t] = gv;
    __syncthreads();
    #pragma unroll
    for (int s = 32; s > 0; s >>= 1) {
        if (t < s) red[t] = fmaxf(red[t], red[t + s]);
        __syncthreads();
    }
    const float mx = red[0];
    __syncthreads();
    const float e = expf(gv - mx);
    red[t] = e;
    __syncthreads();
    #pragma unroll
    for (int s = 32; s > 0; s >>= 1) {
        if (t < s) red[t] += red[t + s];
        __syncthreads();
    }
    const float inv = 1.0f / red[0];
    w2t_buf[(size_t)d * KLT + l * 64 + t] = leaf_weight[base] * e * inv;
}

// ---------------- deterministic split-K reduce ----------------
__global__ __launch_bounds__(256)
void reduce_kernel(float* __restrict__ out) {
    const int i = blockIdx.x * blockDim.x + threadIdx.x;
    const size_t S = (size_t)BATCH * LDIM;
    float a = 0.0f;
    #pragma unroll
    for (int z = 0; z < SPLITK2; z++) a += part_buf[(size_t)z * S + i];
    out[i] = a;
}

// ============================================================================
extern "C" void kernel_launch(void* const* d_in, const int* in_sizes, int n_in,
                              void* d_out, int out_size) {
    (void)in_sizes; (void)n_in; (void)out_size;
    const float* x     = (const float*)d_in[0];
    const float* W     = (const float*)d_in[1];
    const float* bias  = (const float*)d_in[2];
    const float* lw    = (const float*)d_in[3];
    const float* gates = (const float*)d_in[4];
    float* out = (float*)d_out;

    transw_kernel<<<dim3(64, 16), 256>>>(W);
    w2_kernel<<<64 * LDIM, 64>>>(lw, gates);

    hmma_kernel<1><<<dim3(GCOLS / BN, BATCH / BM, 1), 256>>>(x, bias);

    prop_kernel<<<(BATCH * NTREES) / 256, 256>>>();

    hmma_kernel<2><<<dim3(1, BATCH / BM, SPLITK2), 256>>>(nullptr, nullptr);

    reduce_kernel<<<(BATCH * LDIM) / 256, 256>>>(out);
}

// round 4
// speedup vs baseline: 3.5053x; 2.0300x over previous
#include <cuda_runtime.h>
#include <cuda_fp16.h>
#include <cstdint>

typedef unsigned long long u64;
typedef unsigned int u32;

#define BATCH   4096
#define DIN     512
#define NTREES  64
#define NCOLSV  4032        // valid gate columns
#define GCOLS   4096        // padded gate columns
#define KLT     4096
#define LDIM    128
#define SPLITK2 8

// ---------------- scratch (device globals: allocation-free) ----------------
__device__ float  g_buf[(size_t)BATCH * GCOLS];     // sigmoid gates [b][col] fp32
__device__ __half xh_buf[(size_t)BATCH * DIN];      // x hi
__device__ __half xl_buf[(size_t)BATCH * DIN];      // x lo residual
__device__ __half wth_buf[(size_t)GCOLS * DIN];     // W transposed [col][k] hi only
__device__ __half ph_buf[(size_t)BATCH * KLT];      // leaf probs hi
__device__ __half pl_buf[(size_t)BATCH * KLT];      // leaf probs lo
__device__ __half w2th_buf[(size_t)LDIM * KLT];     // leaf_w*softmax transposed hi only
__device__ float  part_buf[SPLITK2 * (size_t)BATCH * LDIM];

// ---------------- helpers ----------------
__device__ __forceinline__ u32 smem_u32(const void* p) {
    u32 a;
    asm("{ .reg .u64 t; cvta.to.shared.u64 t, %1; cvt.u32.u64 %0, t; }" : "=r"(a) : "l"(p));
    return a;
}
__device__ __forceinline__ float sigf(float z) { return 1.0f / (1.0f + expf(-z)); }

#define LDSM_X4(r0, r1, r2, r3, addr) \
    asm volatile("ldmatrix.sync.aligned.m8n8.x4.shared.b16 {%0,%1,%2,%3}, [%4];" \
                 : "=r"(r0), "=r"(r1), "=r"(r2), "=r"(r3) : "r"(addr))

#define MMA16816(d, a, b0, b1) \
    asm volatile("mma.sync.aligned.m16n8k16.row.col.f32.f16.f16.f32 " \
                 "{%0,%1,%2,%3}, {%4,%5,%6,%7}, {%8,%9}, {%0,%1,%2,%3};" \
                 : "+f"((d)[0]), "+f"((d)[1]), "+f"((d)[2]), "+f"((d)[3]) \
                 : "r"((a)[0]), "r"((a)[1]), "r"((a)[2]), "r"((a)[3]), \
                   "r"(b0), "r"(b1))

#define CPA(dst, src) \
    asm volatile("cp.async.cg.shared.global [%0], [%1], 16;" :: "r"(dst), "l"(src))
#define CP_COMMIT() asm volatile("cp.async.commit_group;" ::: "memory")
#define CP_WAIT1()  asm volatile("cp.async.wait_group 1;" ::: "memory")
#define CP_WAIT0()  asm volatile("cp.async.wait_group 0;" ::: "memory")

// ---------------- fp16x2 tensor-core GEMM ----------------
// C[128,128] CTA tile, 8 warps of 64x32, K-chunks of 32, 2-stage cp.async pipeline.
// SMEM tiles per stage: AH, AL, BH; each [128 rows][32 k] fp16 = 8KB.
// Swizzle: 16B chunk c' = c ^ ((row>>1)&3); row stride 64B.
#define BM 128
#define BN 128
#define KC 32
#define T_AH 0
#define T_AL 8192
#define T_BH 16384
#define STG_B 24576
#define OFF_BIAS 49152
#define SMEM_TOTAL (OFF_BIAS + 512)

// MODE 1: g = sigmoid(x @ wt^T + bias)      grid (32, 32, 1)
// MODE 2: part[z] = p @ w2t^T (split-K)     grid (1, 32, 8)
template <int MODE>
__global__ __launch_bounds__(256)
void hmma_kernel(const float* __restrict__ bias) {
    extern __shared__ char smem[];
    const u32 sb = smem_u32(smem);
    const int tid  = threadIdx.x;
    const int wid  = tid >> 5;
    const int lane = tid & 31;

    const int bn = blockIdx.x * BN;
    const int bm = blockIdx.y * BM;
    const long kbase = (long)blockIdx.z * 512;

    const __half* Ah = (MODE == 1) ? xh_buf  : ph_buf;
    const __half* Al = (MODE == 1) ? xl_buf  : pl_buf;
    const __half* Bh = (MODE == 1) ? wth_buf : w2th_buf;
    const long lda = (MODE == 1) ? (long)DIN : (long)KLT;
    const long ldb = (MODE == 1) ? (long)DIN : (long)KLT;

    if (MODE == 1 && tid < 128) {
        int col = bn + tid;
        ((float*)(smem + OFF_BIAS))[tid] = (col < NCOLSV) ? bias[col] : 0.0f;
    }

    // ---- cp.async mapping: thread -> (row r0 / r0+64, 16B chunk cc)
    const int r0 = tid >> 2;
    const int cc = tid & 3;
    const u32 so = (u32)(r0 * 64 + ((cc ^ ((r0 >> 1) & 3)) << 4));   // +4096 for row+64

    const __half* gA0 = Ah + (size_t)(bm + r0) * lda + kbase + cc * 8;
    const __half* gA1 = gA0 + 64 * lda;
    const __half* gL0 = Al + (size_t)(bm + r0) * lda + kbase + cc * 8;
    const __half* gL1 = gL0 + 64 * lda;
    const __half* gB0 = Bh + (size_t)(bn + r0) * ldb + kbase + cc * 8;
    const __half* gB1 = gB0 + 64 * ldb;

    // ---- ldmatrix addressing (per warp), offsets relative to tile base
    const int mw = (wid & 1) * 64;
    const int nw = (wid >> 1) * 32;
    const int rowA_l = mw + (lane & 15);
    const int rowB_l = (lane & 7) | ((lane >> 1) & 8);
    u32 aoff[2], boff[2];
    #pragma unroll
    for (int kk = 0; kk < 2; kk++) {
        int chA = kk * 2 + (lane >> 4);
        int chB = kk * 2 + ((lane >> 3) & 1);
        aoff[kk] = (u32)(rowA_l * 64 + ((chA ^ ((rowA_l >> 1) & 3)) << 4));
        boff[kk] = (u32)(rowB_l * 64 + ((chB ^ ((rowB_l >> 1) & 3)) << 4)) + (u32)(nw * 64);
    }

    float acc[4][4][4];
    #pragma unroll
    for (int i = 0; i < 4; i++)
        #pragma unroll
        for (int j = 0; j < 4; j++)
            #pragma unroll
            for (int e = 0; e < 4; e++) acc[i][j][e] = 0.0f;

    const int NCH = 16;  // K = 512 per CTA

    // prologue: issue chunk 0 into stage 0
    {
        const u32 base = sb;
        CPA(base + T_AH + so,        gA0);
        CPA(base + T_AH + so + 4096, gA1);
        CPA(base + T_AL + so,        gL0);
        CPA(base + T_AL + so + 4096, gL1);
        CPA(base + T_BH + so,        gB0);
        CPA(base + T_BH + so + 4096, gB1);
        CP_COMMIT();
    }

    for (int c = 0; c < NCH; c++) {
        if (c + 1 < NCH) {
            const u32 base = sb + ((c + 1) & 1) * STG_B;
            const int o = (c + 1) * KC;
            CPA(base + T_AH + so,        gA0 + o);
            CPA(base + T_AH + so + 4096, gA1 + o);
            CPA(base + T_AL + so,        gL0 + o);
            CPA(base + T_AL + so + 4096, gL1 + o);
            CPA(base + T_BH + so,        gB0 + o);
            CPA(base + T_BH + so + 4096, gB1 + o);
            CP_COMMIT();
            CP_WAIT1();
        } else {
            CP_WAIT0();
        }
        __syncthreads();

        const u32 tb = sb + (c & 1) * STG_B;
        #pragma unroll
        for (int kk = 0; kk < 2; kk++) {
            u32 Af[4][4], Bv[8];
            #pragma unroll
            for (int f = 0; f < 4; f++)
                LDSM_X4(Af[f][0], Af[f][1], Af[f][2], Af[f][3],
                        tb + T_AH + aoff[kk] + (u32)(f * 1024));
            #pragma unroll
            for (int gi = 0; gi < 2; gi++)
                LDSM_X4(Bv[4 * gi], Bv[4 * gi + 1], Bv[4 * gi + 2], Bv[4 * gi + 3],
                        tb + T_BH + boff[kk] + (u32)(gi * 1024));
            #pragma unroll
            for (int f = 0; f < 4; f++)
                #pragma unroll
                for (int n = 0; n < 4; n++)
                    MMA16816(acc[f][n], Af[f], Bv[2 * n], Bv[2 * n + 1]);

            #pragma unroll
            for (int f = 0; f < 4; f++)
                LDSM_X4(Af[f][0], Af[f][1], Af[f][2], Af[f][3],
                        tb + T_AL + aoff[kk] + (u32)(f * 1024));
            #pragma unroll
            for (int f = 0; f < 4; f++)
                #pragma unroll
                for (int n = 0; n < 4; n++)
                    MMA16816(acc[f][n], Af[f], Bv[2 * n], Bv[2 * n + 1]);
        }
        __syncthreads();
    }

    // ---- epilogue
    const float* bias_s = (const float*)(smem + OFF_BIAS);
    #pragma unroll
    for (int f = 0; f < 4; f++) {
        #pragma unroll
        for (int half = 0; half < 2; half++) {
            const int row_l = mw + f * 16 + (lane >> 2) + half * 8;
            #pragma unroll
            for (int n = 0; n < 4; n++) {
                const int col_l = nw + n * 8 + 2 * (lane & 3);
                float v0 = acc[f][n][2 * half + 0];
                float v1 = acc[f][n][2 * half + 1];
                if (MODE == 1) {
                    v0 = sigf(v0 + bias_s[col_l]);
                    v1 = sigf(v1 + bias_s[col_l + 1]);
                    float* o = g_buf + (size_t)(bm + row_l) * GCOLS + bn + col_l;
                    *(float2*)o = make_float2(v0, v1);
                } else {
                    float* o = part_buf + (size_t)blockIdx.z * (BATCH * LDIM)
                             + (size_t)(bm + row_l) * LDIM + bn + col_l;
                    *(float2*)o = make_float2(v0, v1);
                }
            }
        }
    }
}

// ---------------- x -> fp16 hi/lo split ----------------
__global__ __launch_bounds__(256)
void convx_kernel(const float* __restrict__ x) {
    const int i = blockIdx.x * blockDim.x + threadIdx.x;   // one float4 each
    float4 v = ((const float4*)x)[i];
    __half hx = __float2half_rn(v.x), hy = __float2half_rn(v.y);
    __half hz = __float2half_rn(v.z), hw = __float2half_rn(v.w);
    __half lx = __float2half_rn(v.x - __half2float(hx));
    __half ly = __float2half_rn(v.y - __half2float(hy));
    __half lz = __float2half_rn(v.z - __half2float(hz));
    __half lw = __float2half_rn(v.w - __half2float(hw));
    ((__half2*)xh_buf)[2 * i]     = __halves2half2(hx, hy);
    ((__half2*)xh_buf)[2 * i + 1] = __halves2half2(hz, hw);
    ((__half2*)xl_buf)[2 * i]     = __halves2half2(lx, ly);
    ((__half2*)xl_buf)[2 * i + 1] = __halves2half2(lz, lw);
}

// ---------------- W transpose -> fp16: wth[col][k] = W[n][k][t], pad cols ----------------
__global__ __launch_bounds__(256)
void transw_kernel(const float* __restrict__ W) {
    const int tid = threadIdx.x;
    const int n = blockIdx.x;      // 0..63 (63 = zero-fill)
    const int kb = blockIdx.y;     // 0..15 (32 k each)
    if (n == 63) {
        #pragma unroll
        for (int i = 0; i < 8; i++) {
            int idx = i * 256 + tid;
            int r = idx >> 5, kk = idx & 31;
            wth_buf[(size_t)(4032 + r) * DIN + kb * 32 + kk] = __float2half_rn(0.0f);
        }
        return;
    }
    __shared__ float ts[32][65];
    const int t = tid & 63;
    const int kk0 = tid >> 6;
    #pragma unroll
    for (int i = 0; i < 8; i++) {
        int kk = kk0 + 4 * i;
        ts[kk][t] = W[(size_t)n * (DIN * NTREES) + (size_t)(kb * 32 + kk) * NTREES + t];
    }
    __syncthreads();
    const int kk = tid & 31;
    const int t0 = tid >> 5;
    #pragma unroll
    for (int i = 0; i < 8; i++) {
        int tt = t0 + 8 * i;
        wth_buf[(size_t)(n * 64 + tt) * DIN + kb * 32 + kk] = __float2half_rn(ts[kk][tt]);
    }
}

// ---------------- tree propagation: thread = (b, t, subtree z), 8 leaves ----------------
__global__ __launch_bounds__(256)
void prop_kernel() {
    const int id = blockIdx.x * blockDim.x + threadIdx.x;  // 0 .. 2M-1
    const int t = id & 63;
    const int z = (id >> 6) & 7;        // level-3 subtree
    const int b = id >> 9;

    const float* g = g_buf + (size_t)b * GCOLS + t;

    // prefix product over levels 0..2 (choices = bits of z, MSB first)
    float pre = 1.0f;
    #pragma unroll
    for (int L = 0; L < 3; L++) {
        const int iL = z >> (3 - L);
        const float gg = g[(size_t)(((1 << L) - 1) + iL) * 64];
        const int bit = (z >> (2 - L)) & 1;
        pre *= bit ? (1.0f - gg) : gg;
    }

    // subtree levels 3..5
    const float g3  = g[(size_t)(7 + z) * 64];
    const float g4a = g[(size_t)(15 + 2 * z) * 64];
    const float g4b = g[(size_t)(15 + 2 * z + 1) * 64];
    float g5[4];
    #pragma unroll
    for (int j = 0; j < 4; j++) g5[j] = g[(size_t)(31 + 4 * z + j) * 64];

    float q3[2], q4[4], q5[8];
    q3[0] = pre * g3;          q3[1] = pre * (1.0f - g3);
    q4[0] = q3[0] * g4a;       q4[1] = q3[0] * (1.0f - g4a);
    q4[2] = q3[1] * g4b;       q4[3] = q3[1] * (1.0f - g4b);
    #pragma unroll
    for (int m = 0; m < 4; m++) {
        q5[2 * m]     = q4[m] * g5[m];
        q5[2 * m + 1] = q4[m] * (1.0f - g5[m]);
    }

    __half* oph = ph_buf + (size_t)b * KLT + (size_t)z * 8 * 64 + t;
    __half* opl = pl_buf + (size_t)b * KLT + (size_t)z * 8 * 64 + t;
    #pragma unroll
    for (int j = 0; j < 8; j++) {
        const float p = q5[j];
        const __half h = __float2half_rn(p);
        const __half l = __float2half_rn(p - __half2float(h));
        oph[(size_t)j * 64] = h;
        opl[(size_t)j * 64] = l;
    }
}

// ---------------- softmax * leaf_weight -> fp16 transposed ----------------
__global__ __launch_bounds__(64)
void w2_kernel(const float* __restrict__ leaf_weight, const float* __restrict__ gates) {
    const int l = blockIdx.x / LDIM;
    const int d = blockIdx.x % LDIM;
    const int t = threadIdx.x;
    const size_t base = ((size_t)l * LDIM + d) * NTREES + t;
    const float gv = gates[base];
    __shared__ float red[64];
    red[t] = gv;
    __syncthreads();
    #pragma unroll
    for (int s = 32; s > 0; s >>= 1) {
        if (t < s) red[t] = fmaxf(red[t], red[t + s]);
        __syncthreads();
    }
    const float mx = red[0];
    __syncthreads();
    const float e = expf(gv - mx);
    red[t] = e;
    __syncthreads();
    #pragma unroll
    for (int s = 32; s > 0; s >>= 1) {
        if (t < s) red[t] += red[t + s];
        __syncthreads();
    }
    const float inv = 1.0f / red[0];
    w2th_buf[(size_t)d * KLT + l * 64 + t] = __float2half_rn(leaf_weight[base] * e * inv);
}

// ---------------- deterministic split-K reduce ----------------
__global__ __launch_bounds__(256)
void reduce_kernel(float* __restrict__ out) {
    const int i = blockIdx.x * blockDim.x + threadIdx.x;
    const size_t S = (size_t)BATCH * LDIM;
    float a = 0.0f;
    #pragma unroll
    for (int z = 0; z < SPLITK2; z++) a += part_buf[(size_t)z * S + i];
    out[i] = a;
}

// ============================================================================
extern "C" void kernel_launch(void* const* d_in, const int* in_sizes, int n_in,
                              void* d_out, int out_size) {
    (void)in_sizes; (void)n_in; (void)out_size;
    const float* x     = (const float*)d_in[0];
    const float* W     = (const float*)d_in[1];
    const float* bias  = (const float*)d_in[2];
    const float* lw    = (const float*)d_in[3];
    const float* gates = (const float*)d_in[4];
    float* out = (float*)d_out;

    cudaFuncSetAttribute((const void*)hmma_kernel<1>,
                         cudaFuncAttributeMaxDynamicSharedMemorySize, SMEM_TOTAL);
    cudaFuncSetAttribute((const void*)hmma_kernel<2>,
                         cudaFuncAttributeMaxDynamicSharedMemorySize, SMEM_TOTAL);

    convx_kernel<<<(BATCH * DIN / 4) / 256, 256>>>(x);
    transw_kernel<<<dim3(64, 16), 256>>>(W);
    w2_kernel<<<64 * LDIM, 64>>>(lw, gates);

    hmma_kernel<1><<<dim3(GCOLS / BN, BATCH / BM, 1), 256, SMEM_TOTAL>>>(bias);

    prop_kernel<<<(BATCH * NTREES * 8) / 256, 256>>>();

    hmma_kernel<2><<<dim3(1, BATCH / BM, SPLITK2), 256, SMEM_TOTAL>>>(nullptr);

    reduce_kernel<<<(BATCH * LDIM) / 256, 256>>>(out);
}

// round 5
// speedup vs baseline: 3.7090x; 1.0581x over previous
#include <cuda_runtime.h>
#include <cuda_fp16.h>
#include <cstdint>

typedef unsigned long long u64;
typedef unsigned int u32;

#define BATCH   4096
#define DIN     512
#define NTREES  64
#define NCOLSV  4032        // valid gate columns
#define GCOLS   4096        // padded gate columns
#define KLT     4096
#define LDIM    128
#define SPLITK2 8

// ---------------- scratch (device globals: allocation-free) ----------------
__device__ float  g_buf[(size_t)BATCH * GCOLS];     // sigmoid gates [b][col] fp32
__device__ __half xh_buf[(size_t)BATCH * DIN];      // x hi
__device__ __half xl_buf[(size_t)BATCH * DIN];      // x lo residual
__device__ __half wth_buf[(size_t)GCOLS * DIN];     // W transposed [col][k] hi only
__device__ __half ph_buf[(size_t)BATCH * KLT];      // leaf probs hi
__device__ __half pl_buf[(size_t)BATCH * KLT];      // leaf probs lo
__device__ __half w2th_buf[(size_t)LDIM * KLT];     // leaf_w*softmax transposed hi only
__device__ float  part_buf[SPLITK2 * (size_t)BATCH * LDIM];

// ---------------- helpers ----------------
__device__ __forceinline__ u32 smem_u32(const void* p) {
    u32 a;
    asm("{ .reg .u64 t; cvta.to.shared.u64 t, %1; cvt.u32.u64 %0, t; }" : "=r"(a) : "l"(p));
    return a;
}
__device__ __forceinline__ float sigf(float z) { return 1.0f / (1.0f + expf(-z)); }

#define LDSM_X4(r0, r1, r2, r3, addr) \
    asm volatile("ldmatrix.sync.aligned.m8n8.x4.shared.b16 {%0,%1,%2,%3}, [%4];" \
                 : "=r"(r0), "=r"(r1), "=r"(r2), "=r"(r3) : "r"(addr))

#define MMA16816(d, a, b0, b1) \
    asm volatile("mma.sync.aligned.m16n8k16.row.col.f32.f16.f16.f32 " \
                 "{%0,%1,%2,%3}, {%4,%5,%6,%7}, {%8,%9}, {%0,%1,%2,%3};" \
                 : "+f"((d)[0]), "+f"((d)[1]), "+f"((d)[2]), "+f"((d)[3]) \
                 : "r"((a)[0]), "r"((a)[1]), "r"((a)[2]), "r"((a)[3]), \
                   "r"(b0), "r"(b1))

#define CPA(dst, src) \
    asm volatile("cp.async.cg.shared.global [%0], [%1], 16;" :: "r"(dst), "l"(src))
#define CP_COMMIT() asm volatile("cp.async.commit_group;" ::: "memory")
#define CP_WAIT1()  asm volatile("cp.async.wait_group 1;" ::: "memory")

// ---------------- fp16x2 tensor-core GEMM ----------------
// C[128,128] CTA tile, 8 warps of 64x32, K-chunks of 32, 3-stage cp.async
// pipeline with a single __syncthreads per chunk.
// SMEM tiles per stage: AH, AL, BH; each [128 rows][32 k] fp16 = 8KB.
// Swizzle: 16B chunk c' = c ^ ((row>>1)&3); row stride 64B.
#define BM 128
#define BN 128
#define KC 32
#define T_AH 0
#define T_AL 8192
#define T_BH 16384
#define STG_B 24576
#define NSTAGE 3
#define OFF_BIAS (NSTAGE * STG_B)
#define SMEM_TOTAL (OFF_BIAS + 512)

// MODE 1: g = sigmoid(x @ wt^T + bias)      grid (32, 32, 1)
// MODE 2: part[z] = p @ w2t^T (split-K)     grid (1, 32, 8)
template <int MODE>
__global__ __launch_bounds__(256, 2)
void hmma_kernel(const float* __restrict__ bias) {
    extern __shared__ char smem[];
    const u32 sb = smem_u32(smem);
    const int tid  = threadIdx.x;
    const int wid  = tid >> 5;
    const int lane = tid & 31;

    const int bn = blockIdx.x * BN;
    const int bm = blockIdx.y * BM;
    const long kbase = (long)blockIdx.z * 512;

    const __half* Ah = (MODE == 1) ? xh_buf  : ph_buf;
    const __half* Al = (MODE == 1) ? xl_buf  : pl_buf;
    const __half* Bh = (MODE == 1) ? wth_buf : w2th_buf;
    const long lda = (MODE == 1) ? (long)DIN : (long)KLT;
    const long ldb = (MODE == 1) ? (long)DIN : (long)KLT;

    if (MODE == 1 && tid < 128) {
        int col = bn + tid;
        ((float*)(smem + OFF_BIAS))[tid] = (col < NCOLSV) ? bias[col] : 0.0f;
    }

    // ---- cp.async mapping: thread -> (row r0 / r0+64, 16B chunk cc)
    const int r0 = tid >> 2;
    const int cc = tid & 3;
    const u32 so = (u32)(r0 * 64 + ((cc ^ ((r0 >> 1) & 3)) << 4));   // +4096 for row+64

    const __half* gA0 = Ah + (size_t)(bm + r0) * lda + kbase + cc * 8;
    const __half* gA1 = gA0 + 64 * lda;
    const __half* gL0 = Al + (size_t)(bm + r0) * lda + kbase + cc * 8;
    const __half* gL1 = gL0 + 64 * lda;
    const __half* gB0 = Bh + (size_t)(bn + r0) * ldb + kbase + cc * 8;
    const __half* gB1 = gB0 + 64 * ldb;

    // ---- ldmatrix addressing (per warp), offsets relative to tile base
    const int mw = (wid & 1) * 64;
    const int nw = (wid >> 1) * 32;
    const int rowA_l = mw + (lane & 15);
    const int rowB_l = (lane & 7) | ((lane >> 1) & 8);
    u32 aoff[2], boff[2];
    #pragma unroll
    for (int kk = 0; kk < 2; kk++) {
        int chA = kk * 2 + (lane >> 4);
        int chB = kk * 2 + ((lane >> 3) & 1);
        aoff[kk] = (u32)(rowA_l * 64 + ((chA ^ ((rowA_l >> 1) & 3)) << 4));
        boff[kk] = (u32)(rowB_l * 64 + ((chB ^ ((rowB_l >> 1) & 3)) << 4)) + (u32)(nw * 64);
    }

    float acc[4][4][4];
    #pragma unroll
    for (int i = 0; i < 4; i++)
        #pragma unroll
        for (int j = 0; j < 4; j++)
            #pragma unroll
            for (int e = 0; e < 4; e++) acc[i][j][e] = 0.0f;

    const int NCH = 16;  // K = 512 per CTA

    // prologue: issue chunks 0 and 1
    #pragma unroll
    for (int c0 = 0; c0 < 2; c0++) {
        const u32 base = sb + c0 * STG_B;
        const int o = c0 * KC;
        CPA(base + T_AH + so,        gA0 + o);
        CPA(base + T_AH + so + 4096, gA1 + o);
        CPA(base + T_AL + so,        gL0 + o);
        CPA(base + T_AL + so + 4096, gL1 + o);
        CPA(base + T_BH + so,        gB0 + o);
        CPA(base + T_BH + so + 4096, gB1 + o);
        CP_COMMIT();
    }

    int sc = 2;  // next stage slot to fill (cycles 2,0,1,2,...)
    for (int c = 0; c < NCH; c++) {
        CP_WAIT1();          // chunk c resident (newest pending group is c+1/empty)
        __syncthreads();     // everyone done with the stage we are about to overwrite

        // issue chunk c+2 into the stage consumed at iter c-1
        if (c + 2 < NCH) {
            const u32 base = sb + sc * STG_B;
            const int o = (c + 2) * KC;
            CPA(base + T_AH + so,        gA0 + o);
            CPA(base + T_AH + so + 4096, gA1 + o);
            CPA(base + T_AL + so,        gL0 + o);
            CPA(base + T_AL + so + 4096, gL1 + o);
            CPA(base + T_BH + so,        gB0 + o);
            CPA(base + T_BH + so + 4096, gB1 + o);
        }
        CP_COMMIT();         // always commit so wait_group(1) stays uniform
        sc = (sc == 2) ? 0 : sc + 1;

        const u32 tb = sb + (u32)(c % NSTAGE) * STG_B;
        #pragma unroll
        for (int kk = 0; kk < 2; kk++) {
            u32 Af[4][4], Bv[8];
            #pragma unroll
            for (int f = 0; f < 4; f++)
                LDSM_X4(Af[f][0], Af[f][1], Af[f][2], Af[f][3],
                        tb + T_AH + aoff[kk] + (u32)(f * 1024));
            #pragma unroll
            for (int gi = 0; gi < 2; gi++)
                LDSM_X4(Bv[4 * gi], Bv[4 * gi + 1], Bv[4 * gi + 2], Bv[4 * gi + 3],
                        tb + T_BH + boff[kk] + (u32)(gi * 1024));
            #pragma unroll
            for (int f = 0; f < 4; f++)
                #pragma unroll
                for (int n = 0; n < 4; n++)
                    MMA16816(acc[f][n], Af[f], Bv[2 * n], Bv[2 * n + 1]);

            #pragma unroll
            for (int f = 0; f < 4; f++)
                LDSM_X4(Af[f][0], Af[f][1], Af[f][2], Af[f][3],
                        tb + T_AL + aoff[kk] + (u32)(f * 1024));
            #pragma unroll
            for (int f = 0; f < 4; f++)
                #pragma unroll
                for (int n = 0; n < 4; n++)
                    MMA16816(acc[f][n], Af[f], Bv[2 * n], Bv[2 * n + 1]);
        }
    }

    // ---- epilogue
    const float* bias_s = (const float*)(smem + OFF_BIAS);
    #pragma unroll
    for (int f = 0; f < 4; f++) {
        #pragma unroll
        for (int half = 0; half < 2; half++) {
            const int row_l = mw + f * 16 + (lane >> 2) + half * 8;
            #pragma unroll
            for (int n = 0; n < 4; n++) {
                const int col_l = nw + n * 8 + 2 * (lane & 3);
                float v0 = acc[f][n][2 * half + 0];
                float v1 = acc[f][n][2 * half + 1];
                if (MODE == 1) {
                    v0 = sigf(v0 + bias_s[col_l]);
                    v1 = sigf(v1 + bias_s[col_l + 1]);
                    float* o = g_buf + (size_t)(bm + row_l) * GCOLS + bn + col_l;
                    *(float2*)o = make_float2(v0, v1);
                } else {
                    float* o = part_buf + (size_t)blockIdx.z * (BATCH * LDIM)
                             + (size_t)(bm + row_l) * LDIM + bn + col_l;
                    *(float2*)o = make_float2(v0, v1);
                }
            }
        }
    }
}

// ---------------- x -> fp16 hi/lo split ----------------
__global__ __launch_bounds__(256)
void convx_kernel(const float* __restrict__ x) {
    const int i = blockIdx.x * blockDim.x + threadIdx.x;   // one float4 each
    float4 v = ((const float4*)x)[i];
    __half hx = __float2half_rn(v.x), hy = __float2half_rn(v.y);
    __half hz = __float2half_rn(v.z), hw = __float2half_rn(v.w);
    __half lx = __float2half_rn(v.x - __half2float(hx));
    __half ly = __float2half_rn(v.y - __half2float(hy));
    __half lz = __float2half_rn(v.z - __half2float(hz));
    __half lw = __float2half_rn(v.w - __half2float(hw));
    ((__half2*)xh_buf)[2 * i]     = __halves2half2(hx, hy);
    ((__half2*)xh_buf)[2 * i + 1] = __halves2half2(hz, hw);
    ((__half2*)xl_buf)[2 * i]     = __halves2half2(lx, ly);
    ((__half2*)xl_buf)[2 * i + 1] = __halves2half2(lz, lw);
}

// ---------------- W transpose -> fp16: wth[col][k] = W[n][k][t], pad cols ----------------
__global__ __launch_bounds__(256)
void transw_kernel(const float* __restrict__ W) {
    const int tid = threadIdx.x;
    const int n = blockIdx.x;      // 0..63 (63 = zero-fill)
    const int kb = blockIdx.y;     // 0..15 (32 k each)
    if (n == 63) {
        #pragma unroll
        for (int i = 0; i < 8; i++) {
            int idx = i * 256 + tid;
            int r = idx >> 5, kk = idx & 31;
            wth_buf[(size_t)(4032 + r) * DIN + kb * 32 + kk] = __float2half_rn(0.0f);
        }
        return;
    }
    __shared__ float ts[32][65];
    const int t = tid & 63;
    const int kk0 = tid >> 6;
    #pragma unroll
    for (int i = 0; i < 8; i++) {
        int kk = kk0 + 4 * i;
        ts[kk][t] = W[(size_t)n * (DIN * NTREES) + (size_t)(kb * 32 + kk) * NTREES + t];
    }
    __syncthreads();
    const int kk = tid & 31;
    const int t0 = tid >> 5;
    #pragma unroll
    for (int i = 0; i < 8; i++) {
        int tt = t0 + 8 * i;
        wth_buf[(size_t)(n * 64 + tt) * DIN + kb * 32 + kk] = __float2half_rn(ts[kk][tt]);
    }
}

// ---------------- tree propagation: thread = (b, t, subtree z), 8 leaves ----------------
__global__ __launch_bounds__(256)
void prop_kernel() {
    const int id = blockIdx.x * blockDim.x + threadIdx.x;  // 0 .. 2M-1
    const int t = id & 63;
    const int z = (id >> 6) & 7;        // level-3 subtree
    const int b = id >> 9;

    const float* g = g_buf + (size_t)b * GCOLS + t;

    // prefix product over levels 0..2 (choices = bits of z, MSB first)
    float pre = 1.0f;
    #pragma unroll
    for (int L = 0; L < 3; L++) {
        const int iL = z >> (3 - L);
        const float gg = g[(size_t)(((1 << L) - 1) + iL) * 64];
        const int bit = (z >> (2 - L)) & 1;
        pre *= bit ? (1.0f - gg) : gg;
    }

    // subtree levels 3..5
    const float g3  = g[(size_t)(7 + z) * 64];
    const float g4a = g[(size_t)(15 + 2 * z) * 64];
    const float g4b = g[(size_t)(15 + 2 * z + 1) * 64];
    float g5[4];
    #pragma unroll
    for (int j = 0; j < 4; j++) g5[j] = g[(size_t)(31 + 4 * z + j) * 64];

    float q3[2], q4[4], q5[8];
    q3[0] = pre * g3;          q3[1] = pre * (1.0f - g3);
    q4[0] = q3[0] * g4a;       q4[1] = q3[0] * (1.0f - g4a);
    q4[2] = q3[1] * g4b;       q4[3] = q3[1] * (1.0f - g4b);
    #pragma unroll
    for (int m = 0; m < 4; m++) {
        q5[2 * m]     = q4[m] * g5[m];
        q5[2 * m + 1] = q4[m] * (1.0f - g5[m]);
    }

    __half* oph = ph_buf + (size_t)b * KLT + (size_t)z * 8 * 64 + t;
    __half* opl = pl_buf + (size_t)b * KLT + (size_t)z * 8 * 64 + t;
    #pragma unroll
    for (int j = 0; j < 8; j++) {
        const float p = q5[j];
        const __half h = __float2half_rn(p);
        const __half l = __float2half_rn(p - __half2float(h));
        oph[(size_t)j * 64] = h;
        opl[(size_t)j * 64] = l;
    }
}

// ---------------- softmax * leaf_weight -> fp16 transposed (warp shuffle) ----------------
__global__ __launch_bounds__(128)
void w2_kernel(const float* __restrict__ leaf_weight, const float* __restrict__ gates) {
    const int warp = threadIdx.x >> 5;
    const int lane = threadIdx.x & 31;
    const int idx = blockIdx.x * 4 + warp;     // (l,d) pair, 8192 total
    const int l = idx >> 7;
    const int d = idx & 127;

    const size_t base = ((size_t)l * LDIM + d) * NTREES;
    const float2 gv = ((const float2*)(gates + base))[lane];

    float mx = fmaxf(gv.x, gv.y);
    #pragma unroll
    for (int s = 16; s > 0; s >>= 1) mx = fmaxf(mx, __shfl_xor_sync(0xFFFFFFFFu, mx, s));

    const float e0 = expf(gv.x - mx);
    const float e1 = expf(gv.y - mx);
    float sm = e0 + e1;
    #pragma unroll
    for (int s = 16; s > 0; s >>= 1) sm += __shfl_xor_sync(0xFFFFFFFFu, sm, s);
    const float inv = 1.0f / sm;

    const float2 lwv = ((const float2*)(leaf_weight + base))[lane];
    __half2 r = __floats2half2_rn(lwv.x * e0 * inv, lwv.y * e1 * inv);
    ((__half2*)(w2th_buf + (size_t)d * KLT + l * 64))[lane] = r;
}

// ---------------- deterministic split-K reduce ----------------
__global__ __launch_bounds__(256)
void reduce_kernel(float* __restrict__ out) {
    const int i = blockIdx.x * blockDim.x + threadIdx.x;
    const size_t S = (size_t)BATCH * LDIM;
    float a = 0.0f;
    #pragma unroll
    for (int z = 0; z < SPLITK2; z++) a += part_buf[(size_t)z * S + i];
    out[i] = a;
}

// ============================================================================
extern "C" void kernel_launch(void* const* d_in, const int* in_sizes, int n_in,
                              void* d_out, int out_size) {
    (void)in_sizes; (void)n_in; (void)out_size;
    const float* x     = (const float*)d_in[0];
    const float* W     = (const float*)d_in[1];
    const float* bias  = (const float*)d_in[2];
    const float* lw    = (const float*)d_in[3];
    const float* gates = (const float*)d_in[4];
    float* out = (float*)d_out;

    cudaFuncSetAttribute((const void*)hmma_kernel<1>,
                         cudaFuncAttributeMaxDynamicSharedMemorySize, SMEM_TOTAL);
    cudaFuncSetAttribute((const void*)hmma_kernel<2>,
                         cudaFuncAttributeMaxDynamicSharedMemorySize, SMEM_TOTAL);

    convx_kernel<<<(BATCH * DIN / 4) / 256, 256>>>(x);
    transw_kernel<<<dim3(64, 16), 256>>>(W);
    w2_kernel<<<2048, 128>>>(lw, gates);

    hmma_kernel<1><<<dim3(GCOLS / BN, BATCH / BM, 1), 256, SMEM_TOTAL>>>(bias);

    prop_kernel<<<(BATCH * NTREES * 8) / 256, 256>>>();

    hmma_kernel<2><<<dim3(1, BATCH / BM, SPLITK2), 256, SMEM_TOTAL>>>(nullptr);

    reduce_kernel<<<(BATCH * LDIM) / 256, 256>>>(out);
}

// round 6
// speedup vs baseline: 4.8778x; 1.3151x over previous
#include <cuda_runtime.h>
#include <cuda_fp16.h>
#include <cstdint>

typedef unsigned long long u64;
typedef unsigned int u32;

#define BATCH   4096
#define DIN     512
#define NTREES  64
#define NCOLSV  4032        // valid gate columns
#define GCOLS   4096        // padded gate columns
#define KLT     4096
#define LDIM    128
#define SPLITK2 8

// ---------------- scratch (device globals: allocation-free) ----------------
__device__ float  g_buf[(size_t)BATCH * GCOLS];     // sigmoid gates [b][col] fp32
__device__ __half xh_buf[(size_t)BATCH * DIN];      // x fp16
__device__ __half wth_buf[(size_t)GCOLS * DIN];     // W transposed [col][k] fp16
__device__ __half ph_buf[(size_t)BATCH * KLT];      // leaf probs hi
__device__ __half pl_buf[(size_t)BATCH * KLT];      // leaf probs lo residual
__device__ __half w2th_buf[(size_t)LDIM * KLT];     // leaf_w*softmax transposed fp16
__device__ float  part_buf[SPLITK2 * (size_t)BATCH * LDIM];

// ---------------- helpers ----------------
__device__ __forceinline__ u32 smem_u32(const void* p) {
    u32 a;
    asm("{ .reg .u64 t; cvta.to.shared.u64 t, %1; cvt.u32.u64 %0, t; }" : "=r"(a) : "l"(p));
    return a;
}
__device__ __forceinline__ float sigf(float z) { return 1.0f / (1.0f + expf(-z)); }

#define LDSM_X4(r0, r1, r2, r3, addr) \
    asm volatile("ldmatrix.sync.aligned.m8n8.x4.shared.b16 {%0,%1,%2,%3}, [%4];" \
                 : "=r"(r0), "=r"(r1), "=r"(r2), "=r"(r3) : "r"(addr))

#define MMA16816(d, a, b0, b1) \
    asm volatile("mma.sync.aligned.m16n8k16.row.col.f32.f16.f16.f32 " \
                 "{%0,%1,%2,%3}, {%4,%5,%6,%7}, {%8,%9}, {%0,%1,%2,%3};" \
                 : "+f"((d)[0]), "+f"((d)[1]), "+f"((d)[2]), "+f"((d)[3]) \
                 : "r"((a)[0]), "r"((a)[1]), "r"((a)[2]), "r"((a)[3]), \
                   "r"(b0), "r"(b1))

#define CPA(dst, src) \
    asm volatile("cp.async.cg.shared.global [%0], [%1], 16;" :: "r"(dst), "l"(src))
#define CP_COMMIT() asm volatile("cp.async.commit_group;" ::: "memory")
#define CP_WAIT1()  asm volatile("cp.async.wait_group 1;" ::: "memory")

// ---------------- fp16 tensor-core GEMM ----------------
// C[128,128] CTA tile, 8 warps of 64x32, K-chunks of 32, 3-stage cp.async
// pipeline, one __syncthreads per chunk.
// MODE 1 (1 A term): stage = AH(8K) + BH(8K) = 16KB
// MODE 2 (2 A terms): stage = AH + AL + BH = 24KB
// Swizzle: 16B chunk c' = c ^ ((row>>1)&3); row stride 64B.
#define BM 128
#define BN 128
#define KC 32
#define NSTAGE 3

// MODE 1: g = sigmoid(x @ wt^T + bias)      grid (32, 32, 1)
// MODE 2: part[z] = p @ w2t^T (split-K)     grid (1, 32, 8)
template <int MODE>
__global__ __launch_bounds__(256, 2)
void hmma_kernel(const float* __restrict__ bias) {
    constexpr int NT = (MODE == 1) ? 1 : 2;            // A terms
    constexpr u32 T_BH  = (u32)NT * 8192;              // B tile offset in stage
    constexpr u32 STG_B = T_BH + 8192;                 // stage bytes
    constexpr u32 OFF_BIAS = NSTAGE * STG_B;

    extern __shared__ char smem[];
    const u32 sb = smem_u32(smem);
    const int tid  = threadIdx.x;
    const int wid  = tid >> 5;
    const int lane = tid & 31;

    const int bn = blockIdx.x * BN;
    const int bm = blockIdx.y * BM;
    const long kbase = (long)blockIdx.z * 512;

    const __half* Ah = (MODE == 1) ? xh_buf  : ph_buf;
    const __half* Al = (MODE == 1) ? xh_buf  : pl_buf;   // unused in MODE 1
    const __half* Bh = (MODE == 1) ? wth_buf : w2th_buf;
    const long lda = (MODE == 1) ? (long)DIN : (long)KLT;
    const long ldb = (MODE == 1) ? (long)DIN : (long)KLT;

    if (MODE == 1 && tid < 128) {
        int col = bn + tid;
        ((float*)(smem + OFF_BIAS))[tid] = (col < NCOLSV) ? bias[col] : 0.0f;
    }

    // ---- cp.async mapping: thread -> (row r0 / r0+64, 16B chunk cc)
    const int r0 = tid >> 2;
    const int cc = tid & 3;
    const u32 so = (u32)(r0 * 64 + ((cc ^ ((r0 >> 1) & 3)) << 4));   // +4096 for row+64

    const __half* gA0 = Ah + (size_t)(bm + r0) * lda + kbase + cc * 8;
    const __half* gA1 = gA0 + 64 * lda;
    const __half* gL0 = Al + (size_t)(bm + r0) * lda + kbase + cc * 8;
    const __half* gL1 = gL0 + 64 * lda;
    const __half* gB0 = Bh + (size_t)(bn + r0) * ldb + kbase + cc * 8;
    const __half* gB1 = gB0 + 64 * ldb;

    // ---- ldmatrix addressing (per warp), offsets relative to tile base
    const int mw = (wid & 1) * 64;
    const int nw = (wid >> 1) * 32;
    const int rowA_l = mw + (lane & 15);
    const int rowB_l = (lane & 7) | ((lane >> 1) & 8);
    u32 aoff[2], boff[2];
    #pragma unroll
    for (int kk = 0; kk < 2; kk++) {
        int chA = kk * 2 + (lane >> 4);
        int chB = kk * 2 + ((lane >> 3) & 1);
        aoff[kk] = (u32)(rowA_l * 64 + ((chA ^ ((rowA_l >> 1) & 3)) << 4));
        boff[kk] = (u32)(rowB_l * 64 + ((chB ^ ((rowB_l >> 1) & 3)) << 4)) + (u32)(nw * 64);
    }

    float acc[4][4][4];
    #pragma unroll
    for (int i = 0; i < 4; i++)
        #pragma unroll
        for (int j = 0; j < 4; j++)
            #pragma unroll
            for (int e = 0; e < 4; e++) acc[i][j][e] = 0.0f;

    const int NCH = 16;  // K = 512 per CTA

    // prologue: issue chunks 0 and 1
    #pragma unroll
    for (int c0 = 0; c0 < 2; c0++) {
        const u32 base = sb + c0 * STG_B;
        const int o = c0 * KC;
        CPA(base + so,        gA0 + o);
        CPA(base + so + 4096, gA1 + o);
        if (NT == 2) {
            CPA(base + 8192 + so,        gL0 + o);
            CPA(base + 8192 + so + 4096, gL1 + o);
        }
        CPA(base + T_BH + so,        gB0 + o);
        CPA(base + T_BH + so + 4096, gB1 + o);
        CP_COMMIT();
    }

    int sc = 2;  // next stage slot to fill
    for (int c = 0; c < NCH; c++) {
        CP_WAIT1();          // chunk c resident
        __syncthreads();     // stage we're about to overwrite is fully consumed

        if (c + 2 < NCH) {
            const u32 base = sb + sc * STG_B;
            const int o = (c + 2) * KC;
            CPA(base + so,        gA0 + o);
            CPA(base + so + 4096, gA1 + o);
            if (NT == 2) {
                CPA(base + 8192 + so,        gL0 + o);
                CPA(base + 8192 + so + 4096, gL1 + o);
            }
            CPA(base + T_BH + so,        gB0 + o);
            CPA(base + T_BH + so + 4096, gB1 + o);
        }
        CP_COMMIT();         // always commit so wait_group(1) stays uniform
        sc = (sc == 2) ? 0 : sc + 1;

        const u32 tb = sb + (u32)(c % NSTAGE) * STG_B;
        #pragma unroll
        for (int kk = 0; kk < 2; kk++) {
            u32 Af[4][4], Bv[8];
            #pragma unroll
            for (int f = 0; f < 4; f++)
                LDSM_X4(Af[f][0], Af[f][1], Af[f][2], Af[f][3],
                        tb + aoff[kk] + (u32)(f * 1024));
            #pragma unroll
            for (int gi = 0; gi < 2; gi++)
                LDSM_X4(Bv[4 * gi], Bv[4 * gi + 1], Bv[4 * gi + 2], Bv[4 * gi + 3],
                        tb + T_BH + boff[kk] + (u32)(gi * 1024));
            #pragma unroll
            for (int f = 0; f < 4; f++)
                #pragma unroll
                for (int n = 0; n < 4; n++)
                    MMA16816(acc[f][n], Af[f], Bv[2 * n], Bv[2 * n + 1]);

            if (NT == 2) {
                #pragma unroll
                for (int f = 0; f < 4; f++)
                    LDSM_X4(Af[f][0], Af[f][1], Af[f][2], Af[f][3],
                            tb + 8192 + aoff[kk] + (u32)(f * 1024));
                #pragma unroll
                for (int f = 0; f < 4; f++)
                    #pragma unroll
                    for (int n = 0; n < 4; n++)
                        MMA16816(acc[f][n], Af[f], Bv[2 * n], Bv[2 * n + 1]);
            }
        }
    }

    // ---- epilogue
    const float* bias_s = (const float*)(smem + OFF_BIAS);
    #pragma unroll
    for (int f = 0; f < 4; f++) {
        #pragma unroll
        for (int half = 0; half < 2; half++) {
            const int row_l = mw + f * 16 + (lane >> 2) + half * 8;
            #pragma unroll
            for (int n = 0; n < 4; n++) {
                const int col_l = nw + n * 8 + 2 * (lane & 3);
                float v0 = acc[f][n][2 * half + 0];
                float v1 = acc[f][n][2 * half + 1];
                if (MODE == 1) {
                    v0 = sigf(v0 + bias_s[col_l]);
                    v1 = sigf(v1 + bias_s[col_l + 1]);
                    float* o = g_buf + (size_t)(bm + row_l) * GCOLS + bn + col_l;
                    *(float2*)o = make_float2(v0, v1);
                } else {
                    float* o = part_buf + (size_t)blockIdx.z * (BATCH * LDIM)
                             + (size_t)(bm + row_l) * LDIM + bn + col_l;
                    *(float2*)o = make_float2(v0, v1);
                }
            }
        }
    }
}

#define SMEM1 (NSTAGE * 16384 + 512)
#define SMEM2 (NSTAGE * 24576 + 512)

// ---------------- x -> fp16 ----------------
__global__ __launch_bounds__(256)
void convx_kernel(const float* __restrict__ x) {
    const int i = blockIdx.x * blockDim.x + threadIdx.x;   // one float4 each
    float4 v = ((const float4*)x)[i];
    ((__half2*)xh_buf)[2 * i]     = __floats2half2_rn(v.x, v.y);
    ((__half2*)xh_buf)[2 * i + 1] = __floats2half2_rn(v.z, v.w);
}

// ---------------- W transpose -> fp16: wth[col][k] = W[n][k][t], pad cols ----------------
__global__ __launch_bounds__(256)
void transw_kernel(const float* __restrict__ W) {
    const int tid = threadIdx.x;
    const int n = blockIdx.x;      // 0..63 (63 = zero-fill)
    const int kb = blockIdx.y;     // 0..15 (32 k each)
    if (n == 63) {
        #pragma unroll
        for (int i = 0; i < 8; i++) {
            int idx = i * 256 + tid;
            int r = idx >> 5, kk = idx & 31;
            wth_buf[(size_t)(4032 + r) * DIN + kb * 32 + kk] = __float2half_rn(0.0f);
        }
        return;
    }
    __shared__ float ts[32][65];
    const int t = tid & 63;
    const int kk0 = tid >> 6;
    #pragma unroll
    for (int i = 0; i < 8; i++) {
        int kk = kk0 + 4 * i;
        ts[kk][t] = W[(size_t)n * (DIN * NTREES) + (size_t)(kb * 32 + kk) * NTREES + t];
    }
    __syncthreads();
    const int kk = tid & 31;
    const int t0 = tid >> 5;
    #pragma unroll
    for (int i = 0; i < 8; i++) {
        int tt = t0 + 8 * i;
        wth_buf[(size_t)(n * 64 + tt) * DIN + kb * 32 + kk] = __float2half_rn(ts[kk][tt]);
    }
}

// ---------------- tree propagation: thread = (b, t, subtree z), 8 leaves ----------------
__global__ __launch_bounds__(256)
void prop_kernel() {
    const int id = blockIdx.x * blockDim.x + threadIdx.x;  // 0 .. 2M-1
    const int t = id & 63;
    const int z = (id >> 6) & 7;        // level-3 subtree
    const int b = id >> 9;

    const float* g = g_buf + (size_t)b * GCOLS + t;

    // prefix product over levels 0..2 (choices = bits of z, MSB first)
    float pre = 1.0f;
    #pragma unroll
    for (int L = 0; L < 3; L++) {
        const int iL = z >> (3 - L);
        const float gg = g[(size_t)(((1 << L) - 1) + iL) * 64];
        const int bit = (z >> (2 - L)) & 1;
        pre *= bit ? (1.0f - gg) : gg;
    }

    // subtree levels 3..5
    const float g3  = g[(size_t)(7 + z) * 64];
    const float g4a = g[(size_t)(15 + 2 * z) * 64];
    const float g4b = g[(size_t)(15 + 2 * z + 1) * 64];
    float g5[4];
    #pragma unroll
    for (int j = 0; j < 4; j++) g5[j] = g[(size_t)(31 + 4 * z + j) * 64];

    float q3[2], q4[4], q5[8];
    q3[0] = pre * g3;          q3[1] = pre * (1.0f - g3);
    q4[0] = q3[0] * g4a;       q4[1] = q3[0] * (1.0f - g4a);
    q4[2] = q3[1] * g4b;       q4[3] = q3[1] * (1.0f - g4b);
    #pragma unroll
    for (int m = 0; m < 4; m++) {
        q5[2 * m]     = q4[m] * g5[m];
        q5[2 * m + 1] = q4[m] * (1.0f - g5[m]);
    }

    __half* oph = ph_buf + (size_t)b * KLT + (size_t)z * 8 * 64 + t;
    __half* opl = pl_buf + (size_t)b * KLT + (size_t)z * 8 * 64 + t;
    #pragma unroll
    for (int j = 0; j < 8; j++) {
        const float p = q5[j];
        const __half h = __float2half_rn(p);
        const __half l = __float2half_rn(p - __half2float(h));
        oph[(size_t)j * 64] = h;
        opl[(size_t)j * 64] = l;
    }
}

// ---------------- softmax * leaf_weight -> fp16 transposed (warp shuffle) ----------------
__global__ __launch_bounds__(128)
void w2_kernel(const float* __restrict__ leaf_weight, const float* __restrict__ gates) {
    const int warp = threadIdx.x >> 5;
    const int lane = threadIdx.x & 31;
    const int idx = blockIdx.x * 4 + warp;     // (l,d) pair, 8192 total
    const int l = idx >> 7;
    const int d = idx & 127;

    const size_t base = ((size_t)l * LDIM + d) * NTREES;
    const float2 gv = ((const float2*)(gates + base))[lane];

    float mx = fmaxf(gv.x, gv.y);
    #pragma unroll
    for (int s = 16; s > 0; s >>= 1) mx = fmaxf(mx, __shfl_xor_sync(0xFFFFFFFFu, mx, s));

    const float e0 = expf(gv.x - mx);
    const float e1 = expf(gv.y - mx);
    float sm = e0 + e1;
    #pragma unroll
    for (int s = 16; s > 0; s >>= 1) sm += __shfl_xor_sync(0xFFFFFFFFu, sm, s);
    const float inv = 1.0f / sm;

    const float2 lwv = ((const float2*)(leaf_weight + base))[lane];
    __half2 r = __floats2half2_rn(lwv.x * e0 * inv, lwv.y * e1 * inv);
    ((__half2*)(w2th_buf + (size_t)d * KLT + l * 64))[lane] = r;
}

// ---------------- deterministic split-K reduce ----------------
__global__ __launch_bounds__(256)
void reduce_kernel(float* __restrict__ out) {
    const int i = blockIdx.x * blockDim.x + threadIdx.x;
    const size_t S = (size_t)BATCH * LDIM;
    float a = 0.0f;
    #pragma unroll
    for (int z = 0; z < SPLITK2; z++) a += part_buf[(size_t)z * S + i];
    out[i] = a;
}

// ============================================================================
extern "C" void kernel_launch(void* const* d_in, const int* in_sizes, int n_in,
                              void* d_out, int out_size) {
    (void)in_sizes; (void)n_in; (void)out_size;
    const float* x     = (const float*)d_in[0];
    const float* W     = (const float*)d_in[1];
    const float* bias  = (const float*)d_in[2];
    const float* lw    = (const float*)d_in[3];
    const float* gates = (const float*)d_in[4];
    float* out = (float*)d_out;

    cudaFuncSetAttribute((const void*)hmma_kernel<1>,
                         cudaFuncAttributeMaxDynamicSharedMemorySize, SMEM1);
    cudaFuncSetAttribute((const void*)hmma_kernel<2>,
                         cudaFuncAttributeMaxDynamicSharedMemorySize, SMEM2);

    convx_kernel<<<(BATCH * DIN / 4) / 256, 256>>>(x);
    transw_kernel<<<dim3(64, 16), 256>>>(W);
    w2_kernel<<<2048, 128>>>(lw, gates);

    hmma_kernel<1><<<dim3(GCOLS / BN, BATCH / BM, 1), 256, SMEM1>>>(bias);

    prop_kernel<<<(BATCH * NTREES * 8) / 256, 256>>>();

    hmma_kernel<2><<<dim3(1, BATCH / BM, SPLITK2), 256, SMEM2>>>(nullptr);

    reduce_kernel<<<(BATCH * LDIM) / 256, 256>>>(out);
}

// round 7
// speedup vs baseline: 5.5279x; 1.1333x over previous
#include <cuda_runtime.h>
#include <cuda_fp16.h>
#include <cstdint>

typedef unsigned long long u64;
typedef unsigned int u32;

#define BATCH   4096
#define DIN     512
#define NTREES  64
#define NCOLSV  4032        // valid gate columns
#define GCOLS   4096        // padded gate columns
#define KLT     4096
#define LDIM    128
#define SPLITK2 8

// ---------------- scratch (device globals: allocation-free) ----------------
__device__ float  g_buf[(size_t)BATCH * GCOLS];     // sigmoid gates [b][col] fp32
__device__ __half xh_buf[(size_t)BATCH * DIN];      // x fp16
__device__ __half wth_buf[(size_t)GCOLS * DIN];     // W transposed [col][k] fp16
__device__ __half ph_buf[(size_t)BATCH * KLT];      // leaf probs fp16
__device__ __half w2th_buf[(size_t)LDIM * KLT];     // leaf_w*softmax transposed fp16
__device__ float  part_buf[SPLITK2 * (size_t)BATCH * LDIM];

// ---------------- helpers ----------------
__device__ __forceinline__ u32 smem_u32(const void* p) {
    u32 a;
    asm("{ .reg .u64 t; cvta.to.shared.u64 t, %1; cvt.u32.u64 %0, t; }" : "=r"(a) : "l"(p));
    return a;
}
__device__ __forceinline__ float sigf(float z) { return 1.0f / (1.0f + expf(-z)); }

#define LDSM_X4(r0, r1, r2, r3, addr) \
    asm volatile("ldmatrix.sync.aligned.m8n8.x4.shared.b16 {%0,%1,%2,%3}, [%4];" \
                 : "=r"(r0), "=r"(r1), "=r"(r2), "=r"(r3) : "r"(addr))

#define MMA16816(d, a, b0, b1) \
    asm volatile("mma.sync.aligned.m16n8k16.row.col.f32.f16.f16.f32 " \
                 "{%0,%1,%2,%3}, {%4,%5,%6,%7}, {%8,%9}, {%0,%1,%2,%3};" \
                 : "+f"((d)[0]), "+f"((d)[1]), "+f"((d)[2]), "+f"((d)[3]) \
                 : "r"((a)[0]), "r"((a)[1]), "r"((a)[2]), "r"((a)[3]), \
                   "r"(b0), "r"(b1))

#define CPA(dst, src) \
    asm volatile("cp.async.cg.shared.global [%0], [%1], 16;" :: "r"(dst), "l"(src))
#define CP_COMMIT() asm volatile("cp.async.commit_group;" ::: "memory")
#define CP_WAIT1()  asm volatile("cp.async.wait_group 1;" ::: "memory")

// ---------------- fp16 tensor-core GEMM ----------------
// C[128,128] CTA tile, 8 warps of 64x32, K-chunks of 64 (stored as two 32-k
// subtiles with the proven 64B-row swizzle), 3-stage cp.async pipeline,
// one __syncthreads per 64-K chunk.
// Stage layout: A0(8K) A1(8K) B0(8K) B1(8K) = 32KB; 3 stages = 96KB.
// Swizzle within a subtile: 16B chunk c' = c ^ ((row>>1)&3); row stride 64B.
#define BM 128
#define BN 128
#define KC 64
#define NSTAGE 3
#define STG_B 32768u
#define OFF_BIAS (NSTAGE * STG_B)
#define SMEM_GG (OFF_BIAS + 512)

// MODE 1: g = sigmoid(x @ wt^T + bias)      grid (32, 32, 1)
// MODE 2: part[z] = p @ w2t^T (split-K)     grid (1, 32, 8)
template <int MODE>
__global__ __launch_bounds__(256, 2)
void hmma_kernel(const float* __restrict__ bias) {
    extern __shared__ char smem[];
    const u32 sb = smem_u32(smem);
    const int tid  = threadIdx.x;
    const int wid  = tid >> 5;
    const int lane = tid & 31;

    const int bn = blockIdx.x * BN;
    const int bm = blockIdx.y * BM;
    const long kbase = (long)blockIdx.z * 512;

    const __half* Ah = (MODE == 1) ? xh_buf  : ph_buf;
    const __half* Bh = (MODE == 1) ? wth_buf : w2th_buf;
    const long lda = (MODE == 1) ? (long)DIN : (long)KLT;
    const long ldb = (MODE == 1) ? (long)DIN : (long)KLT;

    if (MODE == 1 && tid < 128) {
        int col = bn + tid;
        ((float*)(smem + OFF_BIAS))[tid] = (col < NCOLSV) ? bias[col] : 0.0f;
    }

    // ---- cp.async mapping: thread -> (row r0 / r0+64, 16B chunk cc) per subtile
    const int r0 = tid >> 2;
    const int cc = tid & 3;
    const u32 so = (u32)(r0 * 64 + ((cc ^ ((r0 >> 1) & 3)) << 4));   // +4096 for row+64

    const __half* gA0 = Ah + (size_t)(bm + r0) * lda + kbase + cc * 8;
    const __half* gA1 = gA0 + 64 * lda;
    const __half* gB0 = Bh + (size_t)(bn + r0) * ldb + kbase + cc * 8;
    const __half* gB1 = gB0 + 64 * ldb;

    // ---- ldmatrix addressing (per warp), offsets relative to subtile base
    const int mw = (wid & 1) * 64;
    const int nw = (wid >> 1) * 32;
    const int rowA_l = mw + (lane & 15);
    const int rowB_l = (lane & 7) | ((lane >> 1) & 8);
    u32 aoff[2], boff[2];
    #pragma unroll
    for (int kk = 0; kk < 2; kk++) {
        int chA = kk * 2 + (lane >> 4);
        int chB = kk * 2 + ((lane >> 3) & 1);
        aoff[kk] = (u32)(rowA_l * 64 + ((chA ^ ((rowA_l >> 1) & 3)) << 4));
        boff[kk] = (u32)(rowB_l * 64 + ((chB ^ ((rowB_l >> 1) & 3)) << 4)) + (u32)(nw * 64);
    }

    float acc[4][4][4];
    #pragma unroll
    for (int i = 0; i < 4; i++)
        #pragma unroll
        for (int j = 0; j < 4; j++)
            #pragma unroll
            for (int e = 0; e < 4; e++) acc[i][j][e] = 0.0f;

    const int NCH = 8;   // K = 512 per CTA, 64 per chunk

    // prologue: issue chunks 0 and 1
    #pragma unroll
    for (int c0 = 0; c0 < 2; c0++) {
        const u32 base = sb + c0 * STG_B;
        const int o = c0 * KC;
        CPA(base +     0 + so,        gA0 + o);
        CPA(base +     0 + so + 4096, gA1 + o);
        CPA(base +  8192 + so,        gA0 + o + 32);
        CPA(base +  8192 + so + 4096, gA1 + o + 32);
        CPA(base + 16384 + so,        gB0 + o);
        CPA(base + 16384 + so + 4096, gB1 + o);
        CPA(base + 24576 + so,        gB0 + o + 32);
        CPA(base + 24576 + so + 4096, gB1 + o + 32);
        CP_COMMIT();
    }

    int sc = 2;  // next stage slot to fill
    for (int c = 0; c < NCH; c++) {
        CP_WAIT1();          // chunk c resident
        __syncthreads();     // stage we're about to overwrite is fully consumed

        if (c + 2 < NCH) {
            const u32 base = sb + sc * STG_B;
            const int o = (c + 2) * KC;
            CPA(base +     0 + so,        gA0 + o);
            CPA(base +     0 + so + 4096, gA1 + o);
            CPA(base +  8192 + so,        gA0 + o + 32);
            CPA(base +  8192 + so + 4096, gA1 + o + 32);
            CPA(base + 16384 + so,        gB0 + o);
            CPA(base + 16384 + so + 4096, gB1 + o);
            CPA(base + 24576 + so,        gB0 + o + 32);
            CPA(base + 24576 + so + 4096, gB1 + o + 32);
        }
        CP_COMMIT();         // always commit so wait_group(1) stays uniform
        sc = (sc == 2) ? 0 : sc + 1;

        const u32 tb = sb + (u32)(c % NSTAGE) * STG_B;
        #pragma unroll
        for (int sub = 0; sub < 2; sub++) {
            const u32 ta  = tb + (u32)sub * 8192;
            const u32 tbb = tb + 16384u + (u32)sub * 8192;
            #pragma unroll
            for (int kk = 0; kk < 2; kk++) {
                u32 Af[4][4], Bv[8];
                #pragma unroll
                for (int f = 0; f < 4; f++)
                    LDSM_X4(Af[f][0], Af[f][1], Af[f][2], Af[f][3],
                            ta + aoff[kk] + (u32)(f * 1024));
                #pragma unroll
                for (int gi = 0; gi < 2; gi++)
                    LDSM_X4(Bv[4 * gi], Bv[4 * gi + 1], Bv[4 * gi + 2], Bv[4 * gi + 3],
                            tbb + boff[kk] + (u32)(gi * 1024));
                #pragma unroll
                for (int f = 0; f < 4; f++)
                    #pragma unroll
                    for (int n = 0; n < 4; n++)
                        MMA16816(acc[f][n], Af[f], Bv[2 * n], Bv[2 * n + 1]);
            }
        }
    }

    // ---- epilogue
    const float* bias_s = (const float*)(smem + OFF_BIAS);
    #pragma unroll
    for (int f = 0; f < 4; f++) {
        #pragma unroll
        for (int half = 0; half < 2; half++) {
            const int row_l = mw + f * 16 + (lane >> 2) + half * 8;
            #pragma unroll
            for (int n = 0; n < 4; n++) {
                const int col_l = nw + n * 8 + 2 * (lane & 3);
                float v0 = acc[f][n][2 * half + 0];
                float v1 = acc[f][n][2 * half + 1];
                if (MODE == 1) {
                    v0 = sigf(v0 + bias_s[col_l]);
                    v1 = sigf(v1 + bias_s[col_l + 1]);
                    float* o = g_buf + (size_t)(bm + row_l) * GCOLS + bn + col_l;
                    *(float2*)o = make_float2(v0, v1);
                } else {
                    float* o = part_buf + (size_t)blockIdx.z * (BATCH * LDIM)
                             + (size_t)(bm + row_l) * LDIM + bn + col_l;
                    *(float2*)o = make_float2(v0, v1);
                }
            }
        }
    }
}

// ---------------- x -> fp16 ----------------
__global__ __launch_bounds__(256)
void convx_kernel(const float* __restrict__ x) {
    const int i = blockIdx.x * blockDim.x + threadIdx.x;   // one float4 each
    float4 v = ((const float4*)x)[i];
    ((__half2*)xh_buf)[2 * i]     = __floats2half2_rn(v.x, v.y);
    ((__half2*)xh_buf)[2 * i + 1] = __floats2half2_rn(v.z, v.w);
}

// ---------------- W transpose -> fp16: wth[col][k] = W[n][k][t], pad cols ----------------
__global__ __launch_bounds__(256)
void transw_kernel(const float* __restrict__ W) {
    const int tid = threadIdx.x;
    const int n = blockIdx.x;      // 0..63 (63 = zero-fill)
    const int kb = blockIdx.y;     // 0..15 (32 k each)
    if (n == 63) {
        #pragma unroll
        for (int i = 0; i < 8; i++) {
            int idx = i * 256 + tid;
            int r = idx >> 5, kk = idx & 31;
            wth_buf[(size_t)(4032 + r) * DIN + kb * 32 + kk] = __float2half_rn(0.0f);
        }
        return;
    }
    __shared__ float ts[32][65];
    const int t = tid & 63;
    const int kk0 = tid >> 6;
    #pragma unroll
    for (int i = 0; i < 8; i++) {
        int kk = kk0 + 4 * i;
        ts[kk][t] = W[(size_t)n * (DIN * NTREES) + (size_t)(kb * 32 + kk) * NTREES + t];
    }
    __syncthreads();
    const int kk = tid & 31;
    const int t0 = tid >> 5;
    #pragma unroll
    for (int i = 0; i < 8; i++) {
        int tt = t0 + 8 * i;
        wth_buf[(size_t)(n * 64 + tt) * DIN + kb * 32 + kk] = __float2half_rn(ts[kk][tt]);
    }
}

// ---------------- tree propagation: thread = (b, t, subtree z), 8 leaves ----------------
__global__ __launch_bounds__(256)
void prop_kernel() {
    const int id = blockIdx.x * blockDim.x + threadIdx.x;  // 0 .. 2M-1
    const int t = id & 63;
    const int z = (id >> 6) & 7;        // level-3 subtree
    const int b = id >> 9;

    const float* g = g_buf + (size_t)b * GCOLS + t;

    // prefix product over levels 0..2 (choices = bits of z, MSB first)
    float pre = 1.0f;
    #pragma unroll
    for (int L = 0; L < 3; L++) {
        const int iL = z >> (3 - L);
        const float gg = g[(size_t)(((1 << L) - 1) + iL) * 64];
        const int bit = (z >> (2 - L)) & 1;
        pre *= bit ? (1.0f - gg) : gg;
    }

    // subtree levels 3..5
    const float g3  = g[(size_t)(7 + z) * 64];
    const float g4a = g[(size_t)(15 + 2 * z) * 64];
    const float g4b = g[(size_t)(15 + 2 * z + 1) * 64];
    float g5[4];
    #pragma unroll
    for (int j = 0; j < 4; j++) g5[j] = g[(size_t)(31 + 4 * z + j) * 64];

    float q3[2], q4[4], q5[8];
    q3[0] = pre * g3;          q3[1] = pre * (1.0f - g3);
    q4[0] = q3[0] * g4a;       q4[1] = q3[0] * (1.0f - g4a);
    q4[2] = q3[1] * g4b;       q4[3] = q3[1] * (1.0f - g4b);
    #pragma unroll
    for (int m = 0; m < 4; m++) {
        q5[2 * m]     = q4[m] * g5[m];
        q5[2 * m + 1] = q4[m] * (1.0f - g5[m]);
    }

    __half* oph = ph_buf + (size_t)b * KLT + (size_t)z * 8 * 64 + t;
    #pragma unroll
    for (int j = 0; j < 8; j++)
        oph[(size_t)j * 64] = __float2half_rn(q5[j]);
}

// ---------------- softmax * leaf_weight -> fp16 transposed (warp shuffle) ----------------
__global__ __launch_bounds__(128)
void w2_kernel(const float* __restrict__ leaf_weight, const float* __restrict__ gates) {
    const int warp = threadIdx.x >> 5;
    const int lane = threadIdx.x & 31;
    const int idx = blockIdx.x * 4 + warp;     // (l,d) pair, 8192 total
    const int l = idx >> 7;
    const int d = idx & 127;

    const size_t base = ((size_t)l * LDIM + d) * NTREES;
    const float2 gv = ((const float2*)(gates + base))[lane];

    float mx = fmaxf(gv.x, gv.y);
    #pragma unroll
    for (int s = 16; s > 0; s >>= 1) mx = fmaxf(mx, __shfl_xor_sync(0xFFFFFFFFu, mx, s));

    const float e0 = expf(gv.x - mx);
    const float e1 = expf(gv.y - mx);
    float sm = e0 + e1;
    #pragma unroll
    for (int s = 16; s > 0; s >>= 1) sm += __shfl_xor_sync(0xFFFFFFFFu, sm, s);
    const float inv = 1.0f / sm;

    const float2 lwv = ((const float2*)(leaf_weight + base))[lane];
    __half2 r = __floats2half2_rn(lwv.x * e0 * inv, lwv.y * e1 * inv);
    ((__half2*)(w2th_buf + (size_t)d * KLT + l * 64))[lane] = r;
}

// ---------------- deterministic split-K reduce ----------------
__global__ __launch_bounds__(256)
void reduce_kernel(float* __restrict__ out) {
    const int i = blockIdx.x * blockDim.x + threadIdx.x;
    const size_t S = (size_t)BATCH * LDIM;
    float a = 0.0f;
    #pragma unroll
    for (int z = 0; z < SPLITK2; z++) a += part_buf[(size_t)z * S + i];
    out[i] = a;
}

// ============================================================================
extern "C" void kernel_launch(void* const* d_in, const int* in_sizes, int n_in,
                              void* d_out, int out_size) {
    (void)in_sizes; (void)n_in; (void)out_size;
    const float* x     = (const float*)d_in[0];
    const float* W     = (const float*)d_in[1];
    const float* bias  = (const float*)d_in[2];
    const float* lw    = (const float*)d_in[3];
    const float* gates = (const float*)d_in[4];
    float* out = (float*)d_out;

    cudaFuncSetAttribute((const void*)hmma_kernel<1>,
                         cudaFuncAttributeMaxDynamicSharedMemorySize, SMEM_GG);
    cudaFuncSetAttribute((const void*)hmma_kernel<2>,
                         cudaFuncAttributeMaxDynamicSharedMemorySize, SMEM_GG);

    convx_kernel<<<(BATCH * DIN / 4) / 256, 256>>>(x);
    transw_kernel<<<dim3(64, 16), 256>>>(W);
    w2_kernel<<<2048, 128>>>(lw, gates);

    hmma_kernel<1><<<dim3(GCOLS / BN, BATCH / BM, 1), 256, SMEM_GG>>>(bias);

    prop_kernel<<<(BATCH * NTREES * 8) / 256, 256>>>();

    hmma_kernel<2><<<dim3(1, BATCH / BM, SPLITK2), 256, SMEM_GG>>>(nullptr);

    reduce_kernel<<<(BATCH * LDIM) / 256, 256>>>(out);
}

// round 8
// speedup vs baseline: 6.2590x; 1.1323x over previous
#include <cuda_runtime.h>
#include <cuda_fp16.h>
#include <cstdint>

typedef unsigned long long u64;
typedef unsigned int u32;

#define BATCH   4096
#define DIN     512
#define NTREES  64
#define NCOLSV  4032        // valid gate columns
#define GCOLS   4096        // padded gate columns
#define KLT     4096
#define LDIM    128
#define SPLITK2 8

// ---------------- scratch (device globals: allocation-free) ----------------
__device__ __half g_buf[(size_t)BATCH * GCOLS];     // sigmoid gates [b][col] fp16
__device__ __half xh_buf[(size_t)BATCH * DIN];      // x fp16
__device__ __half wth_buf[(size_t)GCOLS * DIN];     // W transposed [col][k] fp16
__device__ __half ph_buf[(size_t)BATCH * KLT];      // leaf probs fp16
__device__ __half w2th_buf[(size_t)LDIM * KLT];     // leaf_w*softmax transposed fp16
__device__ float  part_buf[SPLITK2 * (size_t)BATCH * LDIM];

// ---------------- helpers ----------------
__device__ __forceinline__ u32 smem_u32(const void* p) {
    u32 a;
    asm("{ .reg .u64 t; cvta.to.shared.u64 t, %1; cvt.u32.u64 %0, t; }" : "=r"(a) : "l"(p));
    return a;
}
__device__ __forceinline__ float sigf(float z) { return 1.0f / (1.0f + expf(-z)); }

#define LDSM_X4(r0, r1, r2, r3, addr) \
    asm volatile("ldmatrix.sync.aligned.m8n8.x4.shared.b16 {%0,%1,%2,%3}, [%4];" \
                 : "=r"(r0), "=r"(r1), "=r"(r2), "=r"(r3) : "r"(addr))

#define MMA16816(d, a, b0, b1) \
    asm volatile("mma.sync.aligned.m16n8k16.row.col.f32.f16.f16.f32 " \
                 "{%0,%1,%2,%3}, {%4,%5,%6,%7}, {%8,%9}, {%0,%1,%2,%3};" \
                 : "+f"((d)[0]), "+f"((d)[1]), "+f"((d)[2]), "+f"((d)[3]) \
                 : "r"((a)[0]), "r"((a)[1]), "r"((a)[2]), "r"((a)[3]), \
                   "r"(b0), "r"(b1))

#define CPA(dst, src) \
    asm volatile("cp.async.cg.shared.global [%0], [%1], 16;" :: "r"(dst), "l"(src))
#define CP_COMMIT() asm volatile("cp.async.commit_group;" ::: "memory")
#define CP_WAIT1()  asm volatile("cp.async.wait_group 1;" ::: "memory")

// ---------------- fp16 tensor-core GEMM (single A term) ----------------
// C[128,128] CTA tile, 8 warps of 64x32, K-chunks of 32, 3-stage cp.async
// pipeline, one __syncthreads per chunk. Stage = AH(8K)+BH(8K) = 16KB.
// Swizzle: 16B chunk c' = c ^ ((row>>1)&3); row stride 64B.
#define BM 128
#define BN 128
#define KC 32
#define NSTAGE 3
#define T_BH   8192u
#define STG_B  16384u
#define OFF_BIAS (NSTAGE * STG_B)
#define SMEM_GG (OFF_BIAS + 512)

// MODE 1: g = sigmoid(x @ wt^T + bias) -> fp16   grid (32, 32, 1)
// MODE 2: part[z] = p @ w2t^T (split-K)          grid (1, 32, 8)
template <int MODE>
__global__ __launch_bounds__(256, 2)
void hmma_kernel(const float* __restrict__ bias) {
    extern __shared__ char smem[];
    const u32 sb = smem_u32(smem);
    const int tid  = threadIdx.x;
    const int wid  = tid >> 5;
    const int lane = tid & 31;

    const int bn = blockIdx.x * BN;
    const int bm = blockIdx.y * BM;
    const long kbase = (long)blockIdx.z * 512;

    const __half* Ah = (MODE == 1) ? xh_buf  : ph_buf;
    const __half* Bh = (MODE == 1) ? wth_buf : w2th_buf;
    const long lda = (MODE == 1) ? (long)DIN : (long)KLT;
    const long ldb = (MODE == 1) ? (long)DIN : (long)KLT;

    if (MODE == 1 && tid < 128) {
        int col = bn + tid;
        ((float*)(smem + OFF_BIAS))[tid] = (col < NCOLSV) ? bias[col] : 0.0f;
    }

    // ---- cp.async mapping: thread -> (row r0 / r0+64, 16B chunk cc)
    const int r0 = tid >> 2;
    const int cc = tid & 3;
    const u32 so = (u32)(r0 * 64 + ((cc ^ ((r0 >> 1) & 3)) << 4));   // +4096 for row+64

    const __half* gA0 = Ah + (size_t)(bm + r0) * lda + kbase + cc * 8;
    const __half* gA1 = gA0 + 64 * lda;
    const __half* gB0 = Bh + (size_t)(bn + r0) * ldb + kbase + cc * 8;
    const __half* gB1 = gB0 + 64 * ldb;

    // ---- ldmatrix addressing (per warp), offsets relative to tile base
    const int mw = (wid & 1) * 64;
    const int nw = (wid >> 1) * 32;
    const int rowA_l = mw + (lane & 15);
    const int rowB_l = (lane & 7) | ((lane >> 1) & 8);
    u32 aoff[2], boff[2];
    #pragma unroll
    for (int kk = 0; kk < 2; kk++) {
        int chA = kk * 2 + (lane >> 4);
        int chB = kk * 2 + ((lane >> 3) & 1);
        aoff[kk] = (u32)(rowA_l * 64 + ((chA ^ ((rowA_l >> 1) & 3)) << 4));
        boff[kk] = (u32)(rowB_l * 64 + ((chB ^ ((rowB_l >> 1) & 3)) << 4)) + (u32)(nw * 64);
    }

    float acc[4][4][4];
    #pragma unroll
    for (int i = 0; i < 4; i++)
        #pragma unroll
        for (int j = 0; j < 4; j++)
            #pragma unroll
            for (int e = 0; e < 4; e++) acc[i][j][e] = 0.0f;

    const int NCH = 16;  // K = 512 per CTA

    // prologue: issue chunks 0 and 1
    #pragma unroll
    for (int c0 = 0; c0 < 2; c0++) {
        const u32 base = sb + c0 * STG_B;
        const int o = c0 * KC;
        CPA(base + so,        gA0 + o);
        CPA(base + so + 4096, gA1 + o);
        CPA(base + T_BH + so,        gB0 + o);
        CPA(base + T_BH + so + 4096, gB1 + o);
        CP_COMMIT();
    }

    int sc = 2;  // next stage slot to fill
    for (int c = 0; c < NCH; c++) {
        CP_WAIT1();          // chunk c resident
        __syncthreads();     // stage we're about to overwrite is fully consumed

        if (c + 2 < NCH) {
            const u32 base = sb + sc * STG_B;
            const int o = (c + 2) * KC;
            CPA(base + so,        gA0 + o);
            CPA(base + so + 4096, gA1 + o);
            CPA(base + T_BH + so,        gB0 + o);
            CPA(base + T_BH + so + 4096, gB1 + o);
        }
        CP_COMMIT();         // always commit so wait_group(1) stays uniform
        sc = (sc == 2) ? 0 : sc + 1;

        const u32 tb = sb + (u32)(c % NSTAGE) * STG_B;
        #pragma unroll
        for (int kk = 0; kk < 2; kk++) {
            u32 Af[4][4], Bv[8];
            #pragma unroll
            for (int f = 0; f < 4; f++)
                LDSM_X4(Af[f][0], Af[f][1], Af[f][2], Af[f][3],
                        tb + aoff[kk] + (u32)(f * 1024));
            #pragma unroll
            for (int gi = 0; gi < 2; gi++)
                LDSM_X4(Bv[4 * gi], Bv[4 * gi + 1], Bv[4 * gi + 2], Bv[4 * gi + 3],
                        tb + T_BH + boff[kk] + (u32)(gi * 1024));
            #pragma unroll
            for (int f = 0; f < 4; f++)
                #pragma unroll
                for (int n = 0; n < 4; n++)
                    MMA16816(acc[f][n], Af[f], Bv[2 * n], Bv[2 * n + 1]);
        }
    }

    // ---- epilogue
    const float* bias_s = (const float*)(smem + OFF_BIAS);
    #pragma unroll
    for (int f = 0; f < 4; f++) {
        #pragma unroll
        for (int half = 0; half < 2; half++) {
            const int row_l = mw + f * 16 + (lane >> 2) + half * 8;
            #pragma unroll
            for (int n = 0; n < 4; n++) {
                const int col_l = nw + n * 8 + 2 * (lane & 3);
                float v0 = acc[f][n][2 * half + 0];
                float v1 = acc[f][n][2 * half + 1];
                if (MODE == 1) {
                    v0 = sigf(v0 + bias_s[col_l]);
                    v1 = sigf(v1 + bias_s[col_l + 1]);
                    __half2* o = (__half2*)(g_buf + (size_t)(bm + row_l) * GCOLS + bn + col_l);
                    *o = __floats2half2_rn(v0, v1);
                } else {
                    float* o = part_buf + (size_t)blockIdx.z * (BATCH * LDIM)
                             + (size_t)(bm + row_l) * LDIM + bn + col_l;
                    *(float2*)o = make_float2(v0, v1);
                }
            }
        }
    }
}

// ---------------- fused preprocessing: convx | transw | w2 ----------------
// grid = 4096 blocks x 256 threads:
//   [0, 2048)    : x -> fp16              (one float4 per thread)
//   [2048, 3072) : W transpose -> fp16    (n = blk/16, kb = blk%16)
//   [3072, 4096) : softmax*leaf_w -> fp16 (8 warps, one (l,d) each)
__global__ __launch_bounds__(256)
void prep_kernel(const float* __restrict__ x, const float* __restrict__ W,
                 const float* __restrict__ leaf_weight, const float* __restrict__ gates) {
    const int blk = blockIdx.x;
    const int tid = threadIdx.x;

    if (blk < 2048) {
        // ---- convx
        const int i = blk * 256 + tid;
        float4 v = ((const float4*)x)[i];
        ((__half2*)xh_buf)[2 * i]     = __floats2half2_rn(v.x, v.y);
        ((__half2*)xh_buf)[2 * i + 1] = __floats2half2_rn(v.z, v.w);
    } else if (blk < 3072) {
        // ---- transw
        const int bb = blk - 2048;
        const int n = bb >> 4;         // 0..63 (63 = zero-fill)
        const int kb = bb & 15;        // 32 k each
        if (n == 63) {
            #pragma unroll
            for (int i = 0; i < 8; i++) {
                int idx = i * 256 + tid;
                int r = idx >> 5, kk = idx & 31;
                wth_buf[(size_t)(4032 + r) * DIN + kb * 32 + kk] = __float2half_rn(0.0f);
            }
            return;
        }
        __shared__ float ts[32][65];
        const int t = tid & 63;
        const int kk0 = tid >> 6;
        #pragma unroll
        for (int i = 0; i < 8; i++) {
            int kk = kk0 + 4 * i;
            ts[kk][t] = W[(size_t)n * (DIN * NTREES) + (size_t)(kb * 32 + kk) * NTREES + t];
        }
        __syncthreads();
        const int kk = tid & 31;
        const int t0 = tid >> 5;
        #pragma unroll
        for (int i = 0; i < 8; i++) {
            int tt = t0 + 8 * i;
            wth_buf[(size_t)(n * 64 + tt) * DIN + kb * 32 + kk] = __float2half_rn(ts[kk][tt]);
        }
    } else {
        // ---- w2 softmax (one warp per (l,d))
        const int warp = tid >> 5;
        const int lane = tid & 31;
        const int idx = (blk - 3072) * 8 + warp;   // 0..8191
        const int l = idx >> 7;
        const int d = idx & 127;

        const size_t base = ((size_t)l * LDIM + d) * NTREES;
        const float2 gv = ((const float2*)(gates + base))[lane];

        float mx = fmaxf(gv.x, gv.y);
        #pragma unroll
        for (int s = 16; s > 0; s >>= 1) mx = fmaxf(mx, __shfl_xor_sync(0xFFFFFFFFu, mx, s));

        const float e0 = expf(gv.x - mx);
        const float e1 = expf(gv.y - mx);
        float sm = e0 + e1;
        #pragma unroll
        for (int s = 16; s > 0; s >>= 1) sm += __shfl_xor_sync(0xFFFFFFFFu, sm, s);
        const float inv = 1.0f / sm;

        const float2 lwv = ((const float2*)(leaf_weight + base))[lane];
        __half2 r = __floats2half2_rn(lwv.x * e0 * inv, lwv.y * e1 * inv);
        ((__half2*)(w2th_buf + (size_t)d * KLT + l * 64))[lane] = r;
    }
}

// ---------------- tree propagation: thread = (b, t, subtree z), 8 leaves ----------------
__global__ __launch_bounds__(256)
void prop_kernel() {
    const int id = blockIdx.x * blockDim.x + threadIdx.x;  // 0 .. 2M-1
    const int t = id & 63;
    const int z = (id >> 6) & 7;        // level-3 subtree
    const int b = id >> 9;

    const __half* g = g_buf + (size_t)b * GCOLS + t;

    // prefix product over levels 0..2 (choices = bits of z, MSB first)
    float pre = 1.0f;
    #pragma unroll
    for (int L = 0; L < 3; L++) {
        const int iL = z >> (3 - L);
        const float gg = __half2float(g[(size_t)(((1 << L) - 1) + iL) * 64]);
        const int bit = (z >> (2 - L)) & 1;
        pre *= bit ? (1.0f - gg) : gg;
    }

    // subtree levels 3..5
    const float g3  = __half2float(g[(size_t)(7 + z) * 64]);
    const float g4a = __half2float(g[(size_t)(15 + 2 * z) * 64]);
    const float g4b = __half2float(g[(size_t)(15 + 2 * z + 1) * 64]);
    float g5[4];
    #pragma unroll
    for (int j = 0; j < 4; j++) g5[j] = __half2float(g[(size_t)(31 + 4 * z + j) * 64]);

    float q3[2], q4[4], q5[8];
    q3[0] = pre * g3;          q3[1] = pre * (1.0f - g3);
    q4[0] = q3[0] * g4a;       q4[1] = q3[0] * (1.0f - g4a);
    q4[2] = q3[1] * g4b;       q4[3] = q3[1] * (1.0f - g4b);
    #pragma unroll
    for (int m = 0; m < 4; m++) {
        q5[2 * m]     = q4[m] * g5[m];
        q5[2 * m + 1] = q4[m] * (1.0f - g5[m]);
    }

    __half* oph = ph_buf + (size_t)b * KLT + (size_t)z * 8 * 64 + t;
    #pragma unroll
    for (int j = 0; j < 8; j++)
        oph[(size_t)j * 64] = __float2half_rn(q5[j]);
}

// ---------------- deterministic split-K reduce ----------------
__global__ __launch_bounds__(256)
void reduce_kernel(float* __restrict__ out) {
    const int i = blockIdx.x * blockDim.x + threadIdx.x;
    const size_t S = (size_t)BATCH * LDIM;
    float a = 0.0f;
    #pragma unroll
    for (int z = 0; z < SPLITK2; z++) a += part_buf[(size_t)z * S + i];
    out[i] = a;
}

// ============================================================================
extern "C" void kernel_launch(void* const* d_in, const int* in_sizes, int n_in,
                              void* d_out, int out_size) {
    (void)in_sizes; (void)n_in; (void)out_size;
    const float* x     = (const float*)d_in[0];
    const float* W     = (const float*)d_in[1];
    const float* bias  = (const float*)d_in[2];
    const float* lw    = (const float*)d_in[3];
    const float* gates = (const float*)d_in[4];
    float* out = (float*)d_out;

    cudaFuncSetAttribute((const void*)hmma_kernel<1>,
                         cudaFuncAttributeMaxDynamicSharedMemorySize, SMEM_GG);
    cudaFuncSetAttribute((const void*)hmma_kernel<2>,
                         cudaFuncAttributeMaxDynamicSharedMemorySize, SMEM_GG);

    prep_kernel<<<4096, 256>>>(x, W, lw, gates);

    hmma_kernel<1><<<dim3(GCOLS / BN, BATCH / BM, 1), 256, SMEM_GG>>>(bias);

    prop_kernel<<<(BATCH * NTREES * 8) / 256, 256>>>();

    hmma_kernel<2><<<dim3(1, BATCH / BM, SPLITK2), 256, SMEM_GG>>>(nullptr);

    reduce_kernel<<<(BATCH * LDIM) / 256, 256>>>(out);
}

// round 9
// speedup vs baseline: 6.2611x; 1.0003x over previous
#include <cuda_runtime.h>
#include <cuda_fp16.h>
#include <cstdint>

typedef unsigned long long u64;
typedef unsigned int u32;

#define BATCH   4096
#define DIN     512
#define NTREES  64
#define NCOLSV  4032        // valid gate columns
#define GCOLS   4096        // padded gate columns
#define KLT     4096
#define LDIM    128
#define SPLITK2 8

// ---------------- scratch (device globals: allocation-free) ----------------
__device__ __half g_buf[(size_t)BATCH * GCOLS];     // sigmoid gates [b][col] fp16
__device__ __half xh_buf[(size_t)BATCH * DIN];      // x fp16
__device__ __half wth_buf[(size_t)GCOLS * DIN];     // W transposed [col][k] fp16
__device__ __half ph_buf[(size_t)BATCH * KLT];      // leaf probs fp16
__device__ __half w2th_buf[(size_t)LDIM * KLT];     // leaf_w*softmax transposed fp16
__device__ float  part_buf[SPLITK2 * (size_t)BATCH * LDIM];

// ---------------- helpers ----------------
__device__ __forceinline__ u32 smem_u32(const void* p) {
    u32 a;
    asm("{ .reg .u64 t; cvta.to.shared.u64 t, %1; cvt.u32.u64 %0, t; }" : "=r"(a) : "l"(p));
    return a;
}
__device__ __forceinline__ float sigf(float z) { return 1.0f / (1.0f + expf(-z)); }

#define LDSM_X4(r0, r1, r2, r3, addr) \
    asm volatile("ldmatrix.sync.aligned.m8n8.x4.shared.b16 {%0,%1,%2,%3}, [%4];" \
                 : "=r"(r0), "=r"(r1), "=r"(r2), "=r"(r3) : "r"(addr))

#define MMA16816(d, a, b0, b1) \
    asm volatile("mma.sync.aligned.m16n8k16.row.col.f32.f16.f16.f32 " \
                 "{%0,%1,%2,%3}, {%4,%5,%6,%7}, {%8,%9}, {%0,%1,%2,%3};" \
                 : "+f"((d)[0]), "+f"((d)[1]), "+f"((d)[2]), "+f"((d)[3]) \
                 : "r"((a)[0]), "r"((a)[1]), "r"((a)[2]), "r"((a)[3]), \
                   "r"(b0), "r"(b1))

#define CPA(dst, src) \
    asm volatile("cp.async.cg.shared.global [%0], [%1], 16;" :: "r"(dst), "l"(src))
#define CP_COMMIT() asm volatile("cp.async.commit_group;" ::: "memory")
#define CP_WAIT3()  asm volatile("cp.async.wait_group 3;" ::: "memory")

// ---------------- fp16 tensor-core GEMM (single A term) ----------------
// C[128,128] CTA tile, 8 warps of 64x32, K-chunks of 32, 5-stage cp.async
// pipeline (4 chunks in flight), one __syncthreads per chunk.
// Stage = AH(8K)+BH(8K) = 16KB; 5 stages = 80KB; 2 CTAs/SM = 164KB.
// Swizzle: 16B chunk c' = c ^ ((row>>1)&3); row stride 64B.
#define BM 128
#define BN 128
#define KC 32
#define NSTAGE 5
#define T_BH   8192u
#define STG_B  16384u
#define OFF_BIAS (NSTAGE * STG_B)
#define SMEM_GG (OFF_BIAS + 512)

// MODE 1: g = sigmoid(x @ wt^T + bias) -> fp16   grid (32, 32, 1)
// MODE 2: part[z] = p @ w2t^T (split-K)          grid (1, 32, 8)
template <int MODE>
__global__ __launch_bounds__(256, 2)
void hmma_kernel(const float* __restrict__ bias) {
    extern __shared__ char smem[];
    const u32 sb = smem_u32(smem);
    const int tid  = threadIdx.x;
    const int wid  = tid >> 5;
    const int lane = tid & 31;

    const int bn = blockIdx.x * BN;
    const int bm = blockIdx.y * BM;
    const long kbase = (long)blockIdx.z * 512;

    const __half* Ah = (MODE == 1) ? xh_buf  : ph_buf;
    const __half* Bh = (MODE == 1) ? wth_buf : w2th_buf;
    const long lda = (MODE == 1) ? (long)DIN : (long)KLT;
    const long ldb = (MODE == 1) ? (long)DIN : (long)KLT;

    if (MODE == 1 && tid < 128) {
        int col = bn + tid;
        ((float*)(smem + OFF_BIAS))[tid] = (col < NCOLSV) ? bias[col] : 0.0f;
    }

    // ---- cp.async mapping: thread -> (row r0 / r0+64, 16B chunk cc)
    const int r0 = tid >> 2;
    const int cc = tid & 3;
    const u32 so = (u32)(r0 * 64 + ((cc ^ ((r0 >> 1) & 3)) << 4));   // +4096 for row+64

    const __half* gA0 = Ah + (size_t)(bm + r0) * lda + kbase + cc * 8;
    const __half* gA1 = gA0 + 64 * lda;
    const __half* gB0 = Bh + (size_t)(bn + r0) * ldb + kbase + cc * 8;
    const __half* gB1 = gB0 + 64 * ldb;

    // ---- ldmatrix addressing (per warp), offsets relative to tile base
    const int mw = (wid & 1) * 64;
    const int nw = (wid >> 1) * 32;
    const int rowA_l = mw + (lane & 15);
    const int rowB_l = (lane & 7) | ((lane >> 1) & 8);
    u32 aoff[2], boff[2];
    #pragma unroll
    for (int kk = 0; kk < 2; kk++) {
        int chA = kk * 2 + (lane >> 4);
        int chB = kk * 2 + ((lane >> 3) & 1);
        aoff[kk] = (u32)(rowA_l * 64 + ((chA ^ ((rowA_l >> 1) & 3)) << 4));
        boff[kk] = (u32)(rowB_l * 64 + ((chB ^ ((rowB_l >> 1) & 3)) << 4)) + (u32)(nw * 64);
    }

    float acc[4][4][4];
    #pragma unroll
    for (int i = 0; i < 4; i++)
        #pragma unroll
        for (int j = 0; j < 4; j++)
            #pragma unroll
            for (int e = 0; e < 4; e++) acc[i][j][e] = 0.0f;

    const int NCH = 16;  // K = 512 per CTA

    // prologue: issue chunks 0..3 (4 groups in flight)
    #pragma unroll
    for (int c0 = 0; c0 < NSTAGE - 1; c0++) {
        const u32 base = sb + c0 * STG_B;
        const int o = c0 * KC;
        CPA(base + so,        gA0 + o);
        CPA(base + so + 4096, gA1 + o);
        CPA(base + T_BH + so,        gB0 + o);
        CPA(base + T_BH + so + 4096, gB1 + o);
        CP_COMMIT();
    }

    int sc = NSTAGE - 1;  // next stage slot to fill
    for (int c = 0; c < NCH; c++) {
        CP_WAIT3();          // chunk c resident (<=3 younger groups pending)
        __syncthreads();     // stage we're about to overwrite is fully consumed

        if (c + NSTAGE - 1 < NCH) {
            const u32 base = sb + sc * STG_B;
            const int o = (c + NSTAGE - 1) * KC;
            CPA(base + so,        gA0 + o);
            CPA(base + so + 4096, gA1 + o);
            CPA(base + T_BH + so,        gB0 + o);
            CPA(base + T_BH + so + 4096, gB1 + o);
        }
        CP_COMMIT();         // always commit so wait_group count stays uniform
        sc = (sc == NSTAGE - 1) ? 0 : sc + 1;

        const u32 tb = sb + (u32)(c % NSTAGE) * STG_B;
        #pragma unroll
        for (int kk = 0; kk < 2; kk++) {
            u32 Af[4][4], Bv[8];
            #pragma unroll
            for (int f = 0; f < 4; f++)
                LDSM_X4(Af[f][0], Af[f][1], Af[f][2], Af[f][3],
                        tb + aoff[kk] + (u32)(f * 1024));
            #pragma unroll
            for (int gi = 0; gi < 2; gi++)
                LDSM_X4(Bv[4 * gi], Bv[4 * gi + 1], Bv[4 * gi + 2], Bv[4 * gi + 3],
                        tb + T_BH + boff[kk] + (u32)(gi * 1024));
            #pragma unroll
            for (int f = 0; f < 4; f++)
                #pragma unroll
                for (int n = 0; n < 4; n++)
                    MMA16816(acc[f][n], Af[f], Bv[2 * n], Bv[2 * n + 1]);
        }
    }

    // ---- epilogue
    const float* bias_s = (const float*)(smem + OFF_BIAS);
    #pragma unroll
    for (int f = 0; f < 4; f++) {
        #pragma unroll
        for (int half = 0; half < 2; half++) {
            const int row_l = mw + f * 16 + (lane >> 2) + half * 8;
            #pragma unroll
            for (int n = 0; n < 4; n++) {
                const int col_l = nw + n * 8 + 2 * (lane & 3);
                float v0 = acc[f][n][2 * half + 0];
                float v1 = acc[f][n][2 * half + 1];
                if (MODE == 1) {
                    v0 = sigf(v0 + bias_s[col_l]);
                    v1 = sigf(v1 + bias_s[col_l + 1]);
                    __half2* o = (__half2*)(g_buf + (size_t)(bm + row_l) * GCOLS + bn + col_l);
                    *o = __floats2half2_rn(v0, v1);
                } else {
                    float* o = part_buf + (size_t)blockIdx.z * (BATCH * LDIM)
                             + (size_t)(bm + row_l) * LDIM + bn + col_l;
                    *(float2*)o = make_float2(v0, v1);
                }
            }
        }
    }
}

// ---------------- fused preprocessing: convx | transw | w2 ----------------
// grid = 4096 blocks x 256 threads:
//   [0, 2048)    : x -> fp16              (one float4 per thread)
//   [2048, 3072) : W transpose -> fp16    (n = blk/16, kb = blk%16)
//   [3072, 4096) : softmax*leaf_w -> fp16 (8 warps, one (l,d) each)
__global__ __launch_bounds__(256)
void prep_kernel(const float* __restrict__ x, const float* __restrict__ W,
                 const float* __restrict__ leaf_weight, const float* __restrict__ gates) {
    const int blk = blockIdx.x;
    const int tid = threadIdx.x;

    if (blk < 2048) {
        // ---- convx
        const int i = blk * 256 + tid;
        float4 v = ((const float4*)x)[i];
        ((__half2*)xh_buf)[2 * i]     = __floats2half2_rn(v.x, v.y);
        ((__half2*)xh_buf)[2 * i + 1] = __floats2half2_rn(v.z, v.w);
    } else if (blk < 3072) {
        // ---- transw
        const int bb = blk - 2048;
        const int n = bb >> 4;         // 0..63 (63 = zero-fill)
        const int kb = bb & 15;        // 32 k each
        if (n == 63) {
            #pragma unroll
            for (int i = 0; i < 8; i++) {
                int idx = i * 256 + tid;
                int r = idx >> 5, kk = idx & 31;
                wth_buf[(size_t)(4032 + r) * DIN + kb * 32 + kk] = __float2half_rn(0.0f);
            }
            return;
        }
        __shared__ float ts[32][65];
        const int t = tid & 63;
        const int kk0 = tid >> 6;
        #pragma unroll
        for (int i = 0; i < 8; i++) {
            int kk = kk0 + 4 * i;
            ts[kk][t] = W[(size_t)n * (DIN * NTREES) + (size_t)(kb * 32 + kk) * NTREES + t];
        }
        __syncthreads();
        const int kk = tid & 31;
        const int t0 = tid >> 5;
        #pragma unroll
        for (int i = 0; i < 8; i++) {
            int tt = t0 + 8 * i;
            wth_buf[(size_t)(n * 64 + tt) * DIN + kb * 32 + kk] = __float2half_rn(ts[kk][tt]);
        }
    } else {
        // ---- w2 softmax (one warp per (l,d))
        const int warp = tid >> 5;
        const int lane = tid & 31;
        const int idx = (blk - 3072) * 8 + warp;   // 0..8191
        const int l = idx >> 7;
        const int d = idx & 127;

        const size_t base = ((size_t)l * LDIM + d) * NTREES;
        const float2 gv = ((const float2*)(gates + base))[lane];

        float mx = fmaxf(gv.x, gv.y);
        #pragma unroll
        for (int s = 16; s > 0; s >>= 1) mx = fmaxf(mx, __shfl_xor_sync(0xFFFFFFFFu, mx, s));

        const float e0 = expf(gv.x - mx);
        const float e1 = expf(gv.y - mx);
        float sm = e0 + e1;
        #pragma unroll
        for (int s = 16; s > 0; s >>= 1) sm += __shfl_xor_sync(0xFFFFFFFFu, sm, s);
        const float inv = 1.0f / sm;

        const float2 lwv = ((const float2*)(leaf_weight + base))[lane];
        __half2 r = __floats2half2_rn(lwv.x * e0 * inv, lwv.y * e1 * inv);
        ((__half2*)(w2th_buf + (size_t)d * KLT + l * 64))[lane] = r;
    }
}

// ---------------- tree propagation: thread = (b, t, subtree z), 8 leaves ----------------
__global__ __launch_bounds__(256)
void prop_kernel() {
    const int id = blockIdx.x * blockDim.x + threadIdx.x;  // 0 .. 2M-1
    const int t = id & 63;
    const int z = (id >> 6) & 7;        // level-3 subtree
    const int b = id >> 9;

    const __half* g = g_buf + (size_t)b * GCOLS + t;

    // prefix product over levels 0..2 (choices = bits of z, MSB first)
    float pre = 1.0f;
    #pragma unroll
    for (int L = 0; L < 3; L++) {
        const int iL = z >> (3 - L);
        const float gg = __half2float(g[(size_t)(((1 << L) - 1) + iL) * 64]);
        const int bit = (z >> (2 - L)) & 1;
        pre *= bit ? (1.0f - gg) : gg;
    }

    // subtree levels 3..5
    const float g3  = __half2float(g[(size_t)(7 + z) * 64]);
    const float g4a = __half2float(g[(size_t)(15 + 2 * z) * 64]);
    const float g4b = __half2float(g[(size_t)(15 + 2 * z + 1) * 64]);
    float g5[4];
    #pragma unroll
    for (int j = 0; j < 4; j++) g5[j] = __half2float(g[(size_t)(31 + 4 * z + j) * 64]);

    float q3[2], q4[4], q5[8];
    q3[0] = pre * g3;          q3[1] = pre * (1.0f - g3);
    q4[0] = q3[0] * g4a;       q4[1] = q3[0] * (1.0f - g4a);
    q4[2] = q3[1] * g4b;       q4[3] = q3[1] * (1.0f - g4b);
    #pragma unroll
    for (int m = 0; m < 4; m++) {
        q5[2 * m]     = q4[m] * g5[m];
        q5[2 * m + 1] = q4[m] * (1.0f - g5[m]);
    }

    __half* oph = ph_buf + (size_t)b * KLT + (size_t)z * 8 * 64 + t;
    #pragma unroll
    for (int j = 0; j < 8; j++)
        oph[(size_t)j * 64] = __float2half_rn(q5[j]);
}

// ---------------- deterministic split-K reduce ----------------
__global__ __launch_bounds__(256)
void reduce_kernel(float* __restrict__ out) {
    const int i = blockIdx.x * blockDim.x + threadIdx.x;
    const size_t S = (size_t)BATCH * LDIM;
    float a = 0.0f;
    #pragma unroll
    for (int z = 0; z < SPLITK2; z++) a += part_buf[(size_t)z * S + i];
    out[i] = a;
}

// ============================================================================
extern "C" void kernel_launch(void* const* d_in, const int* in_sizes, int n_in,
                              void* d_out, int out_size) {
    (void)in_sizes; (void)n_in; (void)out_size;
    const float* x     = (const float*)d_in[0];
    const float* W     = (const float*)d_in[1];
    const float* bias  = (const float*)d_in[2];
    const float* lw    = (const float*)d_in[3];
    const float* gates = (const float*)d_in[4];
    float* out = (float*)d_out;

    cudaFuncSetAttribute((const void*)hmma_kernel<1>,
                         cudaFuncAttributeMaxDynamicSharedMemorySize, SMEM_GG);
    cudaFuncSetAttribute((const void*)hmma_kernel<2>,
                         cudaFuncAttributeMaxDynamicSharedMemorySize, SMEM_GG);

    prep_kernel<<<4096, 256>>>(x, W, lw, gates);

    hmma_kernel<1><<<dim3(GCOLS / BN, BATCH / BM, 1), 256, SMEM_GG>>>(bias);

    prop_kernel<<<(BATCH * NTREES * 8) / 256, 256>>>();

    hmma_kernel<2><<<dim3(1, BATCH / BM, SPLITK2), 256, SMEM_GG>>>(nullptr);

    reduce_kernel<<<(BATCH * LDIM) / 256, 256>>>(out);
}